// round 6
// baseline (speedup 1.0000x reference)
#include <cuda_runtime.h>

typedef unsigned long long u64;

// ---------------- packed f32x2 helpers (sm_103a) ----------------
__device__ __forceinline__ u64 pack2(float x) {
    u64 r; unsigned u = __float_as_uint(x);
    asm("mov.b64 %0, {%1, %2};" : "=l"(r) : "r"(u), "r"(u));
    return r;
}
__device__ __forceinline__ void fma2(u64 &acc, u64 a, u64 b) {
    asm("fma.rn.f32x2 %0, %1, %2, %0;" : "+l"(acc) : "l"(a), "l"(b));
}
__device__ __forceinline__ float2 unpack2(u64 v) {
    unsigned lo, hi;
    asm("mov.b64 {%0, %1}, %2;" : "=r"(lo), "=r"(hi) : "l"(v));
    return make_float2(__uint_as_float(lo), __uint_as_float(hi));
}

// ---------------- problem constants ----------------
#define NB    32          // batch
#define OH1   56          // conv1 output H/W
#define NPIX1 (OH1*OH1)   // 3136
#define N1    (NB*NPIX1)  // 100352
#define K1    243         // 3*9*9
#define K1PAD 248
#define OH2   24          // conv2 output H/W
#define P2    (OH2*OH2)   // 576
#define N2    (NB*P2)     // 18432
#define K2    20736       // 256*81
#define MCH   256
#define RR    32
#define DD    8
#define CC    10
#define OO    16

// ---------------- scratch (static device memory only) ----------------
__device__ __align__(16) float g_h1[NB*MCH*NPIX1];   // conv1 output (relu'd)
__device__ __align__(16) float g_caps[NB*RR*P2*DD];  // squashed primary caps
__device__ __align__(16) float g_w1t[K1PAD*MCH];     // conv1 weights, K-major (padded)
__device__ __align__(16) float g_w2t[K2*MCH];        // conv2 weights, K-major
__device__ __align__(16) float g_WV[NB*RR*CC*DD];    // W . v (per batch)
__device__ __align__(16) float g_G[NB*RR*CC*DD];     // sum_p cw*caps
__device__ __align__(16) float g_v[NB*CC*OO];        // routing output v
__device__ __align__(16) float g_blog[NB*RR*P2*CC];  // routing logits

// ---------------- weight transposes ----------------
__global__ void wt1_kernel(const float* __restrict__ w) {
    int idx = blockIdx.x * 256 + threadIdx.x;
    if (idx >= K1PAD*MCH) return;
    int k = idx >> 8, m = idx & 255;
    float v = 0.f;
    if (k < K1) v = w[m*K1 + k];
    g_w1t[idx] = v;
}
__global__ void wt2_kernel(const float* __restrict__ w) {
    int idx = blockIdx.x * 256 + threadIdx.x;   // grid = K2 blocks, exact
    int k = idx >> 8, m = idx & 255;
    g_w2t[idx] = w[m*K2 + k];
}

// ---------------- implicit-GEMM conv (f32x2 FMA) ----------------
// CONV==1: A = g_w1t [K1PAD,256], B = im2col(Xin) [K1,N1],  out -> g_h1 (relu+bias)
// CONV==2: A = g_w2t [K2,256],    B = im2col(g_h1)[K2,N2],  out -> g_caps layout (bias)
// NOTE: scratch pointers are selected INSIDE device code — __device__ symbols
// must never be passed as kernel arguments from host code.
template<int CONV>
__global__ __launch_bounds__(256, 2)
void gemm_kernel(const float* __restrict__ Xin, const float* __restrict__ bias)
{
    constexpr int KPAD   = (CONV == 1) ? K1PAD : K2;
    constexpr int IW     = (CONV == 1) ? 64 : OH1;          // input row stride
    constexpr int CHSTR  = (CONV == 1) ? 64*64 : OH1*OH1;   // input channel stride
    constexpr int STRIDE = (CONV == 1) ? 1 : 2;
    const float* At   = (CONV == 1) ? g_w1t : g_w2t;
    const float* Bsrc = (CONV == 1) ? Xin   : g_h1;
    float*       Out  = (CONV == 1) ? g_h1  : g_caps;

    __shared__ __align__(16) float As[8][128];
    __shared__ __align__(16) float Bs[8][128];

    const int tid = threadIdx.x;
    const int tx  = tid & 15;
    const int ty  = tid >> 4;
    const int n0  = blockIdx.x * 128;
    const int m0  = blockIdx.y * 128;

    u64 acc[8][4];
#pragma unroll
    for (int i = 0; i < 8; ++i)
#pragma unroll
        for (int j = 0; j < 4; ++j) acc[i][j] = 0ull;

    const int ldk = tid >> 7;    // 0..1
    const int ldn = tid & 127;   // 0..127

    // ---- per-thread im2col stream init (hoisted n-decomposition) ----
    const int ng = n0 + ldn;
    int base;
    {
        if (CONV == 1) {
            int b   = ng / NPIX1;
            int rem = ng - b*NPIX1;
            int oy  = rem / OH1;
            int ox  = rem - oy*OH1;
            base = b*3*CHSTR + oy*IW + ox;
        } else {
            int b   = ng / P2;
            int rem = ng - b*P2;
            int oy  = rem / OH2;
            int ox  = rem - oy*OH2;
            base = b*MCH*CHSTR + (STRIDE*oy)*IW + STRIDE*ox;
        }
    }
    int off[4], kx[4], ky[4];
#pragma unroll
    for (int i = 0; i < 4; ++i) {
        int k0i = ldk + 2*i;          // < 8, so ky=0, kx=k0i
        off[i] = base + k0i;
        kx[i] = k0i;
        ky[i] = 0;
    }
    const float* aA = At + ldk*MCH + m0 + ldn;

#pragma unroll 1
    for (int k0 = 0; k0 < KPAD; k0 += 8) {
        // ---- load A tile [8][128] and B tile (incremental im2col) ----
#pragma unroll
        for (int i = 0; i < 4; ++i) {
            int k = ldk + 2*i;
            As[k][ldn] = aA[i*2*MCH];
            float v = 0.f;
            if (CONV == 1) {
                if (k0 + k < K1) v = Bsrc[off[i]];
            } else {
                v = Bsrc[off[i]];
            }
            Bs[k][ldn] = v;
            // advance stream i by 8 along k = (ic, ky, kx)
            kx[i] += 8; off[i] += 8;
            if (kx[i] >= 9) {
                kx[i] -= 9; off[i] += IW - 9;
                if (++ky[i] >= 9) { ky[i] -= 9; off[i] += CHSTR - 9*IW; }
            }
        }
        aA += 8*MCH;
        __syncthreads();

#pragma unroll
        for (int kk = 0; kk < 8; ++kk) {
            union F4U { float4 f; u64 u[2]; };
            F4U b0, b1, a0, a1;
            b0.f = *(const float4*)&Bs[kk][tx*4];
            b1.f = *(const float4*)&Bs[kk][64 + tx*4];
            a0.f = *(const float4*)&As[kk][ty*4];
            a1.f = *(const float4*)&As[kk][64 + ty*4];
            u64 bb[4] = { b0.u[0], b0.u[1], b1.u[0], b1.u[1] };
            float av[8] = { a0.f.x, a0.f.y, a0.f.z, a0.f.w,
                            a1.f.x, a1.f.y, a1.f.z, a1.f.w };
#pragma unroll
            for (int i = 0; i < 8; ++i) {
                u64 a2 = pack2(av[i]);
#pragma unroll
                for (int j = 0; j < 4; ++j) fma2(acc[i][j], a2, bb[j]);
            }
        }
        __syncthreads();
    }

    // ---- epilogue ----
#pragma unroll
    for (int i = 0; i < 8; ++i) {
        int m = m0 + ((i < 4) ? (ty*4 + i) : (64 + ty*4 + (i - 4)));
        float bv = bias[m];
#pragma unroll
        for (int j = 0; j < 4; ++j) {
            float2 v2 = unpack2(acc[i][j]);
            int ncol = n0 + ((j < 2) ? (tx*4 + 2*j) : (64 + tx*4 + 2*(j - 2)));
#pragma unroll
            for (int e = 0; e < 2; ++e) {
                int n = ncol + e;
                float val = ((e == 0) ? v2.x : v2.y) + bv;
                if (CONV == 1) {
                    int b = n / NPIX1, rem = n - b*NPIX1;
                    val = val > 0.f ? val : 0.f;
                    Out[(b*MCH + m)*NPIX1 + rem] = val;
                } else {
                    int r = m >> 3, d = m & 7;
                    int b = n / P2, p = n - b*P2;
                    Out[(((b*RR + r)*P2) + p)*DD + d] = val;
                }
            }
        }
    }
}

// ---------------- squash primary capsules (in place) ----------------
__global__ void squash_caps_kernel() {
    int v = blockIdx.x * 256 + threadIdx.x;
    if (v >= NB*RR*P2) return;
    float4 lo = *(float4*)&g_caps[v*8];
    float4 hi = *(float4*)&g_caps[v*8 + 4];
    float norm = lo.x*lo.x + lo.y*lo.y + lo.z*lo.z + lo.w*lo.w
               + hi.x*hi.x + hi.y*hi.y + hi.z*hi.z + hi.w*hi.w;
    float scale = norm / ((1.f + norm) * sqrtf(norm + 1e-8f));
    lo.x *= scale; lo.y *= scale; lo.z *= scale; lo.w *= scale;
    hi.x *= scale; hi.y *= scale; hi.z *= scale; hi.w *= scale;
    *(float4*)&g_caps[v*8]     = lo;
    *(float4*)&g_caps[v*8 + 4] = hi;
}

// ---------------- WV[b,r,c,i] = sum_o route_w[r,c,i,o] * v[b,c,o] ----------------
__global__ void wv_kernel(const float* __restrict__ route_w) {
    int idx = blockIdx.x * 128 + threadIdx.x;
    if (idx >= NB*RR*CC*DD) return;
    int b    = idx / (RR*CC*DD);
    int rem  = idx - b*(RR*CC*DD);
    int r    = rem / (CC*DD);
    int rem2 = rem - r*(CC*DD);
    int c    = rem2 / DD;
    int i    = rem2 - c*DD;
    const float* w = route_w + ((r*CC + c)*DD + i)*OO;
    const float* v = g_v + (b*CC + c)*OO;
    float acc = 0.f;
#pragma unroll
    for (int o = 0; o < OO; ++o) acc += w[o] * v[o];
    g_WV[idx] = acc;
}

// ---------------- routing pass: softmax weights + G accumulation ----------------
// MODE 1: cw = 0.1 (softmax of zeros), no logit IO
// MODE 2: b = <u_hat,v1> (prev logits are 0), store to g_blog, cw = softmax(b)
// MODE 3: b = g_blog + <u_hat,v2>, cw = softmax(b)
template<int MODE>
__global__ void pass_kernel() {
    const int b = blockIdx.x, r = blockIdx.y;
    const int tid = threadIdx.x;   // 64 threads
    __shared__ float sWV[CC*DD];
    __shared__ float sG[2][CC*DD];

    if (MODE >= 2) {
        for (int j = tid; j < CC*DD; j += 64)
            sWV[j] = g_WV[(b*RR + r)*CC*DD + j];
    }
    __syncthreads();

    float Gp[CC*DD];
#pragma unroll
    for (int j = 0; j < CC*DD; ++j) Gp[j] = 0.f;

    const float* capbase = g_caps + (size_t)(b*RR + r)*P2*DD;

#pragma unroll 1
    for (int pi = 0; pi < 9; ++pi) {
        int p = pi*64 + tid;
        float4 l0 = *(const float4*)(capbase + p*8);
        float4 l1 = *(const float4*)(capbase + p*8 + 4);
        float cv[8] = { l0.x, l0.y, l0.z, l0.w, l1.x, l1.y, l1.z, l1.w };

        float cw[CC];
        if (MODE == 1) {
#pragma unroll
            for (int c = 0; c < CC; ++c) cw[c] = 0.1f;
        } else {
            float bvv[CC];
            long bidx = ((long)b*RR*P2 + (long)r*P2 + p)*CC;
#pragma unroll
            for (int c = 0; c < CC; ++c) {
                float t = 0.f;
#pragma unroll
                for (int i = 0; i < 8; ++i) t += cv[i] * sWV[c*8 + i];
                bvv[c] = ((MODE == 3) ? g_blog[bidx + c] : 0.f) + t;
                if (MODE == 2) g_blog[bidx + c] = bvv[c];
            }
            float mx = bvv[0];
#pragma unroll
            for (int c = 1; c < CC; ++c) mx = fmaxf(mx, bvv[c]);
            float sum = 0.f;
#pragma unroll
            for (int c = 0; c < CC; ++c) { cw[c] = __expf(bvv[c] - mx); sum += cw[c]; }
            float inv = 1.f / sum;
#pragma unroll
            for (int c = 0; c < CC; ++c) cw[c] *= inv;
        }
#pragma unroll
        for (int c = 0; c < CC; ++c)
#pragma unroll
            for (int i = 0; i < 8; ++i) Gp[c*8 + i] += cw[c] * cv[i];
    }

    // reduce Gp over 64 threads
    int wid = tid >> 5, lane = tid & 31;
#pragma unroll
    for (int j = 0; j < CC*DD; ++j) {
        float val = Gp[j];
#pragma unroll
        for (int s = 16; s > 0; s >>= 1) val += __shfl_xor_sync(0xffffffffu, val, s);
        if (lane == 0) sG[wid][j] = val;
    }
    __syncthreads();
    for (int j = tid; j < CC*DD; j += 64)
        g_G[(b*RR + r)*CC*DD + j] = sG[0][j] + sG[1][j];
}

// ---------------- s = G . W ; v = squash(s) ----------------
__global__ void sv_kernel(const float* __restrict__ route_w, float* __restrict__ dout) {
    const int b = blockIdx.x;
    const int tid = threadIdx.x;     // 160 threads = (c,o)
    __shared__ float sGb[RR*CC*DD];  // 2560 floats
    __shared__ float ss[CC*OO];

    for (int j = tid; j < RR*CC*DD; j += CC*OO) sGb[j] = g_G[b*RR*CC*DD + j];
    __syncthreads();

    const int c = tid / OO, o = tid - (tid / OO)*OO;
    float s = 0.f;
#pragma unroll 1
    for (int r = 0; r < RR; ++r) {
#pragma unroll
        for (int i = 0; i < DD; ++i)
            s += sGb[(r*CC + c)*DD + i] * route_w[((r*CC + c)*DD + i)*OO + o];
    }
    ss[tid] = s;
    __syncthreads();
    float norm = 0.f;
#pragma unroll
    for (int oo = 0; oo < OO; ++oo) { float t = ss[c*OO + oo]; norm += t*t; }
    float scale = norm / ((1.f + norm) * sqrtf(norm + 1e-8f));
    float val = scale * s;
    g_v[b*CC*OO + tid] = val;
    if (dout) dout[b*CC*OO + tid] = val;
}

// ---------------- launcher ----------------
extern "C" void kernel_launch(void* const* d_in, const int* in_sizes, int n_in,
                              void* d_out, int out_size)
{
    // metadata order == setup_inputs order
    const float* x  = (const float*)d_in[0];   // [32,3,64,64]
    const float* w1 = (const float*)d_in[1];   // [256,3,9,9]
    const float* b1 = (const float*)d_in[2];   // [256]
    const float* w2 = (const float*)d_in[3];   // [256,256,9,9]
    const float* b2 = (const float*)d_in[4];   // [256]
    const float* rw = (const float*)d_in[5];   // [32,10,8,16]
    float* out = (float*)d_out;

    // weight transposes (K-major)
    wt1_kernel<<<(K1PAD*MCH + 255)/256, 256>>>(w1);
    wt2_kernel<<<K2, 256>>>(w2);

    // conv1 (implicit GEMM, relu+bias fused) -> g_h1
    gemm_kernel<1><<<dim3(N1/128, 2), 256>>>(x, b1);
    // conv2 (implicit GEMM, bias fused, caps layout) -> g_caps
    gemm_kernel<2><<<dim3(N2/128, 2), 256>>>(nullptr, b2);
    // squash primary caps in place
    squash_caps_kernel<<<(NB*RR*P2 + 255)/256, 256>>>();

    // routing iteration 1 (uniform weights)
    pass_kernel<1><<<dim3(NB, RR), 64>>>();
    sv_kernel<<<NB, CC*OO>>>(rw, nullptr);          // v1
    // routing iteration 2
    wv_kernel<<<(NB*RR*CC*DD + 127)/128, 128>>>(rw);
    pass_kernel<2><<<dim3(NB, RR), 64>>>();
    sv_kernel<<<NB, CC*OO>>>(rw, nullptr);          // v2
    // routing iteration 3 (final)
    wv_kernel<<<(NB*RR*CC*DD + 127)/128, 128>>>(rw);
    pass_kernel<3><<<dim3(NB, RR), 64>>>();
    sv_kernel<<<NB, CC*OO>>>(rw, out);              // v3 -> d_out
    (void)out_size;
}

// round 7
// speedup vs baseline: 1.0742x; 1.0742x over previous
#include <cuda_runtime.h>

typedef unsigned long long u64;

// ---------------- packed f32x2 helpers (sm_103a) ----------------
__device__ __forceinline__ u64 pack2(float x) {
    u64 r; unsigned u = __float_as_uint(x);
    asm("mov.b64 %0, {%1, %2};" : "=l"(r) : "r"(u), "r"(u));
    return r;
}
__device__ __forceinline__ void fma2(u64 &acc, u64 a, u64 b) {
    asm("fma.rn.f32x2 %0, %1, %2, %0;" : "+l"(acc) : "l"(a), "l"(b));
}
__device__ __forceinline__ float2 unpack2(u64 v) {
    unsigned lo, hi;
    asm("mov.b64 {%0, %1}, %2;" : "=r"(lo), "=r"(hi) : "l"(v));
    return make_float2(__uint_as_float(lo), __uint_as_float(hi));
}

// ---------------- cp.async helpers ----------------
__device__ __forceinline__ unsigned smem_u32(const void* p) {
    return (unsigned)__cvta_generic_to_shared(p);
}
__device__ __forceinline__ void cp4(unsigned dst, const float* src, int srcsize) {
    asm volatile("cp.async.ca.shared.global [%0], [%1], 4, %2;"
                 :: "r"(dst), "l"(src), "r"(srcsize));
}
__device__ __forceinline__ void cp4u(unsigned dst, const float* src) {
    asm volatile("cp.async.ca.shared.global [%0], [%1], 4;"
                 :: "r"(dst), "l"(src));
}
__device__ __forceinline__ void cp_commit() {
    asm volatile("cp.async.commit_group;");
}
template<int N>
__device__ __forceinline__ void cp_wait() {
    asm volatile("cp.async.wait_group %0;" :: "n"(N));
}

// ---------------- problem constants ----------------
#define NB    32          // batch
#define OH1   56          // conv1 output H/W
#define NPIX1 (OH1*OH1)   // 3136
#define N1    (NB*NPIX1)  // 100352
#define K1    243         // 3*9*9
#define K1PAD 248
#define OH2   24          // conv2 output H/W
#define P2    (OH2*OH2)   // 576
#define N2    (NB*P2)     // 18432
#define K2    20736       // 256*81
#define MCH   256
#define RR    32
#define DD    8
#define CC    10
#define OO    16

// ---------------- scratch (static device memory only) ----------------
__device__ __align__(16) float g_h1[NB*MCH*NPIX1];   // conv1 output (relu'd)
__device__ __align__(16) float g_caps[NB*RR*P2*DD];  // squashed primary caps
__device__ __align__(16) float g_w1t[K1PAD*MCH];     // conv1 weights, K-major (padded)
__device__ __align__(16) float g_w2t[K2*MCH];        // conv2 weights, K-major
__device__ __align__(16) float g_WV[NB*RR*CC*DD];    // W . v (per batch)
__device__ __align__(16) float g_G[NB*RR*CC*DD];     // sum_p cw*caps
__device__ __align__(16) float g_v[NB*CC*OO];        // routing output v
__device__ __align__(16) float g_blog[NB*RR*P2*CC];  // routing logits

// ---------------- weight transposes ----------------
__global__ void wt1_kernel(const float* __restrict__ w) {
    int idx = blockIdx.x * 256 + threadIdx.x;
    if (idx >= K1PAD*MCH) return;
    int k = idx >> 8, m = idx & 255;
    float v = 0.f;
    if (k < K1) v = w[m*K1 + k];
    g_w1t[idx] = v;
}
__global__ void wt2_kernel(const float* __restrict__ w) {
    int idx = blockIdx.x * 256 + threadIdx.x;   // grid = K2 blocks, exact
    int k = idx >> 8, m = idx & 255;
    g_w2t[idx] = w[m*K2 + k];
}

// ---------------- implicit-GEMM conv (f32x2 FMA, 3-stage cp.async pipeline) ----------------
// CONV==1: A = g_w1t [K1PAD,256], B = im2col(Xin) [K1,N1],  out -> g_h1 (relu+bias)
// CONV==2: A = g_w2t [K2,256],    B = im2col(g_h1)[K2,N2],  out -> g_caps layout (bias)
// NOTE: scratch pointers are selected INSIDE device code — __device__ symbols
// must never be passed as kernel arguments from host code.
template<int CONV>
__global__ __launch_bounds__(256, 2)
void gemm_kernel(const float* __restrict__ Xin, const float* __restrict__ bias)
{
    constexpr int KPAD   = (CONV == 1) ? K1PAD : K2;
    constexpr int NT     = KPAD / 8;                        // k-tiles
    constexpr int IW     = (CONV == 1) ? 64 : OH1;          // input row stride
    constexpr int CHSTR  = (CONV == 1) ? 64*64 : OH1*OH1;   // input channel stride
    constexpr int STRIDE = (CONV == 1) ? 1 : 2;
    const float* At   = (CONV == 1) ? g_w1t : g_w2t;
    const float* Bsrc = (CONV == 1) ? Xin   : g_h1;
    float*       Out  = (CONV == 1) ? g_h1  : g_caps;

    __shared__ __align__(16) float As[3][8][128];
    __shared__ __align__(16) float Bs[3][8][128];

    const int tid = threadIdx.x;
    const int tx  = tid & 15;
    const int ty  = tid >> 4;
    const int n0  = blockIdx.x * 128;
    const int m0  = blockIdx.y * 128;

    u64 acc[8][4];
#pragma unroll
    for (int i = 0; i < 8; ++i)
#pragma unroll
        for (int j = 0; j < 4; ++j) acc[i][j] = 0ull;

    const int ldk = tid >> 7;    // 0..1
    const int ldn = tid & 127;   // 0..127

    // ---- per-thread im2col stream init (hoisted n-decomposition) ----
    const int ng = n0 + ldn;
    int base;
    {
        if (CONV == 1) {
            int b   = ng / NPIX1;
            int rem = ng - b*NPIX1;
            int oy  = rem / OH1;
            int ox  = rem - oy*OH1;
            base = b*3*CHSTR + oy*IW + ox;
        } else {
            int b   = ng / P2;
            int rem = ng - b*P2;
            int oy  = rem / OH2;
            int ox  = rem - oy*OH2;
            base = b*MCH*CHSTR + (STRIDE*oy)*IW + STRIDE*ox;
        }
    }
    int off[4], kx[4], ky[4];
#pragma unroll
    for (int i = 0; i < 4; ++i) {
        int k0i = ldk + 2*i;          // < 8, so ky=0, kx=k0i
        off[i] = base + k0i;
        kx[i] = k0i;
        ky[i] = 0;
    }
    const float* aA = At + ldk*MCH + m0 + ldn;
    int kpref = 0;   // k0 of the next tile to prefetch

    // issue one k-tile's loads into stage s, then commit the group
    auto PREFETCH = [&](int s) {
#pragma unroll
        for (int i = 0; i < 4; ++i) {
            int k = ldk + 2*i;
            cp4u(smem_u32(&As[s][k][ldn]), aA + i*2*MCH);
            if (CONV == 1) {
                // zero-fill past K1 (src-size = 0), keep address valid
                int ok = (kpref + k < K1);
                cp4(smem_u32(&Bs[s][k][ldn]), Bsrc + (ok ? off[i] : 0), ok ? 4 : 0);
            } else {
                cp4u(smem_u32(&Bs[s][k][ldn]), Bsrc + off[i]);
            }
            // advance stream i by 8 along k = (ic, ky, kx)
            kx[i] += 8; off[i] += 8;
            if (kx[i] >= 9) {
                kx[i] -= 9; off[i] += IW - 9;
                if (++ky[i] >= 9) { ky[i] -= 9; off[i] += CHSTR - 9*IW; }
            }
        }
        aA += 8*MCH;
        kpref += 8;
        cp_commit();
    };

    // prologue: tiles 0 and 1 in flight
    PREFETCH(0);
    PREFETCH(1);

#pragma unroll 1
    for (int it = 0; it < NT; ++it) {
        cp_wait<1>();        // tile `it` landed (only tile it+1 may be in flight)
        __syncthreads();     // all warps done with stage (it+2)%3's previous contents
        if (it + 2 < NT) PREFETCH((it + 2) % 3);
        else             cp_commit();          // keep group numbering aligned
        const int s = it % 3;

#pragma unroll
        for (int kk = 0; kk < 8; ++kk) {
            union F4U { float4 f; u64 u[2]; };
            F4U b0, b1, a0, a1;
            b0.f = *(const float4*)&Bs[s][kk][tx*4];
            b1.f = *(const float4*)&Bs[s][kk][64 + tx*4];
            a0.f = *(const float4*)&As[s][kk][ty*4];
            a1.f = *(const float4*)&As[s][kk][64 + ty*4];
            u64 bb[4] = { b0.u[0], b0.u[1], b1.u[0], b1.u[1] };
            float av[8] = { a0.f.x, a0.f.y, a0.f.z, a0.f.w,
                            a1.f.x, a1.f.y, a1.f.z, a1.f.w };
#pragma unroll
            for (int i = 0; i < 8; ++i) {
                u64 a2 = pack2(av[i]);
#pragma unroll
                for (int j = 0; j < 4; ++j) fma2(acc[i][j], a2, bb[j]);
            }
        }
    }

    // ---- epilogue ----
#pragma unroll
    for (int i = 0; i < 8; ++i) {
        int m = m0 + ((i < 4) ? (ty*4 + i) : (64 + ty*4 + (i - 4)));
        float bv = bias[m];
#pragma unroll
        for (int j = 0; j < 4; ++j) {
            float2 v2 = unpack2(acc[i][j]);
            int ncol = n0 + ((j < 2) ? (tx*4 + 2*j) : (64 + tx*4 + 2*(j - 2)));
#pragma unroll
            for (int e = 0; e < 2; ++e) {
                int n = ncol + e;
                float val = ((e == 0) ? v2.x : v2.y) + bv;
                if (CONV == 1) {
                    int b = n / NPIX1, rem = n - b*NPIX1;
                    val = val > 0.f ? val : 0.f;
                    Out[(b*MCH + m)*NPIX1 + rem] = val;
                } else {
                    int r = m >> 3, d = m & 7;
                    int b = n / P2, p = n - b*P2;
                    Out[(((b*RR + r)*P2) + p)*DD + d] = val;
                }
            }
        }
    }
}

// ---------------- squash primary capsules (in place) ----------------
__global__ void squash_caps_kernel() {
    int v = blockIdx.x * 256 + threadIdx.x;
    if (v >= NB*RR*P2) return;
    float4 lo = *(float4*)&g_caps[v*8];
    float4 hi = *(float4*)&g_caps[v*8 + 4];
    float norm = lo.x*lo.x + lo.y*lo.y + lo.z*lo.z + lo.w*lo.w
               + hi.x*hi.x + hi.y*hi.y + hi.z*hi.z + hi.w*hi.w;
    float scale = norm / ((1.f + norm) * sqrtf(norm + 1e-8f));
    lo.x *= scale; lo.y *= scale; lo.z *= scale; lo.w *= scale;
    hi.x *= scale; hi.y *= scale; hi.z *= scale; hi.w *= scale;
    *(float4*)&g_caps[v*8]     = lo;
    *(float4*)&g_caps[v*8 + 4] = hi;
}

// ---------------- WV[b,r,c,i] = sum_o route_w[r,c,i,o] * v[b,c,o] ----------------
__global__ void wv_kernel(const float* __restrict__ route_w) {
    int idx = blockIdx.x * 128 + threadIdx.x;
    if (idx >= NB*RR*CC*DD) return;
    int b    = idx / (RR*CC*DD);
    int rem  = idx - b*(RR*CC*DD);
    int r    = rem / (CC*DD);
    int rem2 = rem - r*(CC*DD);
    int c    = rem2 / DD;
    int i    = rem2 - c*DD;
    const float* w = route_w + ((r*CC + c)*DD + i)*OO;
    const float* v = g_v + (b*CC + c)*OO;
    float acc = 0.f;
#pragma unroll
    for (int o = 0; o < OO; ++o) acc += w[o] * v[o];
    g_WV[idx] = acc;
}

// ---------------- routing pass: softmax weights + G accumulation ----------------
// MODE 1: cw = 0.1 (softmax of zeros), no logit IO
// MODE 2: b = <u_hat,v1> (prev logits are 0), store to g_blog, cw = softmax(b)
// MODE 3: b = g_blog + <u_hat,v2>, cw = softmax(b)
template<int MODE>
__global__ void pass_kernel() {
    const int b = blockIdx.x, r = blockIdx.y;
    const int tid = threadIdx.x;   // 64 threads
    __shared__ float sWV[CC*DD];
    __shared__ float sG[2][CC*DD];

    if (MODE >= 2) {
        for (int j = tid; j < CC*DD; j += 64)
            sWV[j] = g_WV[(b*RR + r)*CC*DD + j];
    }
    __syncthreads();

    float Gp[CC*DD];
#pragma unroll
    for (int j = 0; j < CC*DD; ++j) Gp[j] = 0.f;

    const float* capbase = g_caps + (size_t)(b*RR + r)*P2*DD;

#pragma unroll 1
    for (int pi = 0; pi < 9; ++pi) {
        int p = pi*64 + tid;
        float4 l0 = *(const float4*)(capbase + p*8);
        float4 l1 = *(const float4*)(capbase + p*8 + 4);
        float cv[8] = { l0.x, l0.y, l0.z, l0.w, l1.x, l1.y, l1.z, l1.w };

        float cw[CC];
        if (MODE == 1) {
#pragma unroll
            for (int c = 0; c < CC; ++c) cw[c] = 0.1f;
        } else {
            float bvv[CC];
            long bidx = ((long)b*RR*P2 + (long)r*P2 + p)*CC;
#pragma unroll
            for (int c = 0; c < CC; ++c) {
                float t = 0.f;
#pragma unroll
                for (int i = 0; i < 8; ++i) t += cv[i] * sWV[c*8 + i];
                bvv[c] = ((MODE == 3) ? g_blog[bidx + c] : 0.f) + t;
                if (MODE == 2) g_blog[bidx + c] = bvv[c];
            }
            float mx = bvv[0];
#pragma unroll
            for (int c = 1; c < CC; ++c) mx = fmaxf(mx, bvv[c]);
            float sum = 0.f;
#pragma unroll
            for (int c = 0; c < CC; ++c) { cw[c] = __expf(bvv[c] - mx); sum += cw[c]; }
            float inv = 1.f / sum;
#pragma unroll
            for (int c = 0; c < CC; ++c) cw[c] *= inv;
        }
#pragma unroll
        for (int c = 0; c < CC; ++c)
#pragma unroll
            for (int i = 0; i < 8; ++i) Gp[c*8 + i] += cw[c] * cv[i];
    }

    // reduce Gp over 64 threads
    int wid = tid >> 5, lane = tid & 31;
#pragma unroll
    for (int j = 0; j < CC*DD; ++j) {
        float val = Gp[j];
#pragma unroll
        for (int s = 16; s > 0; s >>= 1) val += __shfl_xor_sync(0xffffffffu, val, s);
        if (lane == 0) sG[wid][j] = val;
    }
    __syncthreads();
    for (int j = tid; j < CC*DD; j += 64)
        g_G[(b*RR + r)*CC*DD + j] = sG[0][j] + sG[1][j];
}

// ---------------- s = G . W ; v = squash(s) ----------------
__global__ void sv_kernel(const float* __restrict__ route_w, float* __restrict__ dout) {
    const int b = blockIdx.x;
    const int tid = threadIdx.x;     // 160 threads = (c,o)
    __shared__ float sGb[RR*CC*DD];  // 2560 floats
    __shared__ float ss[CC*OO];

    for (int j = tid; j < RR*CC*DD; j += CC*OO) sGb[j] = g_G[b*RR*CC*DD + j];
    __syncthreads();

    const int c = tid / OO, o = tid - (tid / OO)*OO;
    float s = 0.f;
#pragma unroll 1
    for (int r = 0; r < RR; ++r) {
#pragma unroll
        for (int i = 0; i < DD; ++i)
            s += sGb[(r*CC + c)*DD + i] * route_w[((r*CC + c)*DD + i)*OO + o];
    }
    ss[tid] = s;
    __syncthreads();
    float norm = 0.f;
#pragma unroll
    for (int oo = 0; oo < OO; ++oo) { float t = ss[c*OO + oo]; norm += t*t; }
    float scale = norm / ((1.f + norm) * sqrtf(norm + 1e-8f));
    float val = scale * s;
    g_v[b*CC*OO + tid] = val;
    if (dout) dout[b*CC*OO + tid] = val;
}

// ---------------- launcher ----------------
extern "C" void kernel_launch(void* const* d_in, const int* in_sizes, int n_in,
                              void* d_out, int out_size)
{
    // metadata order == setup_inputs order
    const float* x  = (const float*)d_in[0];   // [32,3,64,64]
    const float* w1 = (const float*)d_in[1];   // [256,3,9,9]
    const float* b1 = (const float*)d_in[2];   // [256]
    const float* w2 = (const float*)d_in[3];   // [256,256,9,9]
    const float* b2 = (const float*)d_in[4];   // [256]
    const float* rw = (const float*)d_in[5];   // [32,10,8,16]
    float* out = (float*)d_out;

    // weight transposes (K-major)
    wt1_kernel<<<(K1PAD*MCH + 255)/256, 256>>>(w1);
    wt2_kernel<<<K2, 256>>>(w2);

    // conv1 (implicit GEMM, relu+bias fused) -> g_h1
    gemm_kernel<1><<<dim3(N1/128, 2), 256>>>(x, b1);
    // conv2 (implicit GEMM, bias fused, caps layout) -> g_caps
    gemm_kernel<2><<<dim3(N2/128, 2), 256>>>(nullptr, b2);
    // squash primary caps in place
    squash_caps_kernel<<<(NB*RR*P2 + 255)/256, 256>>>();

    // routing iteration 1 (uniform weights)
    pass_kernel<1><<<dim3(NB, RR), 64>>>();
    sv_kernel<<<NB, CC*OO>>>(rw, nullptr);          // v1
    // routing iteration 2
    wv_kernel<<<(NB*RR*CC*DD + 127)/128, 128>>>(rw);
    pass_kernel<2><<<dim3(NB, RR), 64>>>();
    sv_kernel<<<NB, CC*OO>>>(rw, nullptr);          // v2
    // routing iteration 3 (final)
    wv_kernel<<<(NB*RR*CC*DD + 127)/128, 128>>>(rw);
    pass_kernel<3><<<dim3(NB, RR), 64>>>();
    sv_kernel<<<NB, CC*OO>>>(rw, out);              // v3 -> d_out
    (void)out_size;
}

// round 8
// speedup vs baseline: 1.0744x; 1.0002x over previous
#include <cuda_runtime.h>

typedef unsigned long long u64;

// ---------------- packed f32x2 helpers (sm_103a) ----------------
__device__ __forceinline__ u64 pack2(float x) {
    u64 r; unsigned u = __float_as_uint(x);
    asm("mov.b64 %0, {%1, %2};" : "=l"(r) : "r"(u), "r"(u));
    return r;
}
__device__ __forceinline__ void fma2(u64 &acc, u64 a, u64 b) {
    asm("fma.rn.f32x2 %0, %1, %2, %0;" : "+l"(acc) : "l"(a), "l"(b));
}
__device__ __forceinline__ float2 unpack2(u64 v) {
    unsigned lo, hi;
    asm("mov.b64 {%0, %1}, %2;" : "=r"(lo), "=r"(hi) : "l"(v));
    return make_float2(__uint_as_float(lo), __uint_as_float(hi));
}

// ---------------- cp.async helpers ----------------
__device__ __forceinline__ unsigned smem_u32(const void* p) {
    return (unsigned)__cvta_generic_to_shared(p);
}
__device__ __forceinline__ void cp4(unsigned dst, const float* src, int srcsize) {
    asm volatile("cp.async.ca.shared.global [%0], [%1], 4, %2;"
                 :: "r"(dst), "l"(src), "r"(srcsize));
}
__device__ __forceinline__ void cp4u(unsigned dst, const float* src) {
    asm volatile("cp.async.ca.shared.global [%0], [%1], 4;"
                 :: "r"(dst), "l"(src));
}
__device__ __forceinline__ void cp_commit() {
    asm volatile("cp.async.commit_group;");
}
template<int N>
__device__ __forceinline__ void cp_wait() {
    asm volatile("cp.async.wait_group %0;" :: "n"(N));
}

// ---------------- problem constants ----------------
#define NB    32          // batch
#define OH1   56          // conv1 output H/W
#define NPIX1 (OH1*OH1)   // 3136
#define N1    (NB*NPIX1)  // 100352
#define K1    243         // 3*9*9
#define K1PAD 248
#define OH2   24          // conv2 output H/W
#define P2    (OH2*OH2)   // 576
#define N2    (NB*P2)     // 18432
#define K2    20736       // 256*81
#define MCH   256
#define RR    32
#define DD    8
#define CC    10
#define OO    16

// ---------------- scratch (static device memory only) ----------------
__device__ __align__(16) float g_h1[NB*MCH*NPIX1];   // conv1 output (relu'd)
__device__ __align__(16) float g_caps[NB*RR*P2*DD];  // squashed primary caps
__device__ __align__(16) float g_w1t[K1PAD*MCH];     // conv1 weights, K-major (padded)
__device__ __align__(16) float g_w2t[K2*MCH];        // conv2 weights, K-major
__device__ __align__(16) float g_WV[NB*RR*CC*DD];    // W . v (per batch)
__device__ __align__(16) float g_G[NB*RR*CC*DD];     // sum_p cw*caps
__device__ __align__(16) float g_v[NB*CC*OO];        // routing output v
__device__ __align__(16) float g_blog[NB*RR*P2*CC];  // routing logits

// ---------------- weight transposes ----------------
__global__ void wt1_kernel(const float* __restrict__ w) {
    int idx = blockIdx.x * 256 + threadIdx.x;
    if (idx >= K1PAD*MCH) return;
    int k = idx >> 8, m = idx & 255;
    float v = 0.f;
    if (k < K1) v = w[m*K1 + k];
    g_w1t[idx] = v;
}
__global__ void wt2_kernel(const float* __restrict__ w) {
    int idx = blockIdx.x * 256 + threadIdx.x;   // grid = K2 blocks, exact
    int k = idx >> 8, m = idx & 255;
    g_w2t[idx] = w[m*K2 + k];
}

// ---------------- implicit-GEMM conv (f32x2 FMA, 3-stage cp.async pipeline) ----------------
// CONV==1: A = g_w1t [K1PAD,256], B = im2col(Xin) [K1,N1],  out -> g_h1 (relu+bias)
// CONV==2: A = g_w2t [K2,256],    B = im2col(g_h1)[K2,N2],  out -> g_caps layout (bias)
// NOTE: scratch pointers are selected INSIDE device code — __device__ symbols
// must never be passed as kernel arguments from host code.
template<int CONV>
__global__ __launch_bounds__(256, 2)
void gemm_kernel(const float* __restrict__ Xin, const float* __restrict__ bias)
{
    constexpr int KPAD   = (CONV == 1) ? K1PAD : K2;
    constexpr int NT     = KPAD / 8;                        // k-tiles
    constexpr int IW     = (CONV == 1) ? 64 : OH1;          // input row stride
    constexpr int CHSTR  = (CONV == 1) ? 64*64 : OH1*OH1;   // input channel stride
    constexpr int STRIDE = (CONV == 1) ? 1 : 2;
    const float* At   = (CONV == 1) ? g_w1t : g_w2t;
    const float* Bsrc = (CONV == 1) ? Xin   : g_h1;
    float*       Out  = (CONV == 1) ? g_h1  : g_caps;

    __shared__ __align__(16) float As[3][8][128];
    __shared__ __align__(16) float Bs[3][8][128];

    const int tid = threadIdx.x;
    const int tx  = tid & 15;
    const int ty  = tid >> 4;
    const int n0  = blockIdx.x * 128;
    const int m0  = blockIdx.y * 128;

    u64 acc[8][4];
#pragma unroll
    for (int i = 0; i < 8; ++i)
#pragma unroll
        for (int j = 0; j < 4; ++j) acc[i][j] = 0ull;

    const int ldk = tid >> 7;    // 0..1
    const int ldn = tid & 127;   // 0..127

    // ---- per-thread im2col stream init (hoisted n-decomposition) ----
    const int ng = n0 + ldn;
    int base;
    {
        if (CONV == 1) {
            int b   = ng / NPIX1;
            int rem = ng - b*NPIX1;
            int oy  = rem / OH1;
            int ox  = rem - oy*OH1;
            base = b*3*CHSTR + oy*IW + ox;
        } else {
            int b   = ng / P2;
            int rem = ng - b*P2;
            int oy  = rem / OH2;
            int ox  = rem - oy*OH2;
            base = b*MCH*CHSTR + (STRIDE*oy)*IW + STRIDE*ox;
        }
    }
    int off[4], kx[4], ky[4];
#pragma unroll
    for (int i = 0; i < 4; ++i) {
        int k0i = ldk + 2*i;          // < 8, so ky=0, kx=k0i
        off[i] = base + k0i;
        kx[i] = k0i;
        ky[i] = 0;
    }
    const float* aA = At + ldk*MCH + m0 + ldn;
    int kpref = 0;   // k0 of the next tile to prefetch

    // issue one k-tile's loads into stage s, then commit the group
    auto PREFETCH = [&](int s) {
#pragma unroll
        for (int i = 0; i < 4; ++i) {
            int k = ldk + 2*i;
            cp4u(smem_u32(&As[s][k][ldn]), aA + i*2*MCH);
            if (CONV == 1) {
                // zero-fill past K1 (src-size = 0), keep address valid
                int ok = (kpref + k < K1);
                cp4(smem_u32(&Bs[s][k][ldn]), Bsrc + (ok ? off[i] : 0), ok ? 4 : 0);
            } else {
                cp4u(smem_u32(&Bs[s][k][ldn]), Bsrc + off[i]);
            }
            // advance stream i by 8 along k = (ic, ky, kx)
            kx[i] += 8; off[i] += 8;
            if (kx[i] >= 9) {
                kx[i] -= 9; off[i] += IW - 9;
                if (++ky[i] >= 9) { ky[i] -= 9; off[i] += CHSTR - 9*IW; }
            }
        }
        aA += 8*MCH;
        kpref += 8;
        cp_commit();
    };

    // prologue: tiles 0 and 1 in flight
    PREFETCH(0);
    PREFETCH(1);

#pragma unroll 1
    for (int it = 0; it < NT; ++it) {
        cp_wait<1>();        // tile `it` landed (only tile it+1 may be in flight)
        __syncthreads();     // all warps done with stage (it+2)%3's previous contents
        if (it + 2 < NT) PREFETCH((it + 2) % 3);
        else             cp_commit();          // keep group numbering aligned
        const int s = it % 3;

#pragma unroll
        for (int kk = 0; kk < 8; ++kk) {
            union F4U { float4 f; u64 u[2]; };
            F4U b0, b1, a0, a1;
            b0.f = *(const float4*)&Bs[s][kk][tx*4];
            b1.f = *(const float4*)&Bs[s][kk][64 + tx*4];
            a0.f = *(const float4*)&As[s][kk][ty*4];
            a1.f = *(const float4*)&As[s][kk][64 + ty*4];
            u64 bb[4] = { b0.u[0], b0.u[1], b1.u[0], b1.u[1] };
            float av[8] = { a0.f.x, a0.f.y, a0.f.z, a0.f.w,
                            a1.f.x, a1.f.y, a1.f.z, a1.f.w };
#pragma unroll
            for (int i = 0; i < 8; ++i) {
                u64 a2 = pack2(av[i]);
#pragma unroll
                for (int j = 0; j < 4; ++j) fma2(acc[i][j], a2, bb[j]);
            }
        }
    }

    // ---- epilogue ----
#pragma unroll
    for (int i = 0; i < 8; ++i) {
        int m = m0 + ((i < 4) ? (ty*4 + i) : (64 + ty*4 + (i - 4)));
        float bv = bias[m];
#pragma unroll
        for (int j = 0; j < 4; ++j) {
            float2 v2 = unpack2(acc[i][j]);
            int ncol = n0 + ((j < 2) ? (tx*4 + 2*j) : (64 + tx*4 + 2*(j - 2)));
#pragma unroll
            for (int e = 0; e < 2; ++e) {
                int n = ncol + e;
                float val = ((e == 0) ? v2.x : v2.y) + bv;
                if (CONV == 1) {
                    int b = n / NPIX1, rem = n - b*NPIX1;
                    val = val > 0.f ? val : 0.f;
                    Out[(b*MCH + m)*NPIX1 + rem] = val;
                } else {
                    int r = m >> 3, d = m & 7;
                    int b = n / P2, p = n - b*P2;
                    Out[(((b*RR + r)*P2) + p)*DD + d] = val;
                }
            }
        }
    }
}

// ---------------- squash primary capsules (in place) ----------------
__global__ void squash_caps_kernel() {
    int v = blockIdx.x * 256 + threadIdx.x;
    if (v >= NB*RR*P2) return;
    float4 lo = *(float4*)&g_caps[v*8];
    float4 hi = *(float4*)&g_caps[v*8 + 4];
    float norm = lo.x*lo.x + lo.y*lo.y + lo.z*lo.z + lo.w*lo.w
               + hi.x*hi.x + hi.y*hi.y + hi.z*hi.z + hi.w*hi.w;
    float scale = norm / ((1.f + norm) * sqrtf(norm + 1e-8f));
    lo.x *= scale; lo.y *= scale; lo.z *= scale; lo.w *= scale;
    hi.x *= scale; hi.y *= scale; hi.z *= scale; hi.w *= scale;
    *(float4*)&g_caps[v*8]     = lo;
    *(float4*)&g_caps[v*8 + 4] = hi;
}

// ---------------- WV[b,r,c,i] = sum_o route_w[r,c,i,o] * v[b,c,o] ----------------
__global__ void wv_kernel(const float* __restrict__ route_w) {
    int idx = blockIdx.x * 128 + threadIdx.x;
    if (idx >= NB*RR*CC*DD) return;
    int b    = idx / (RR*CC*DD);
    int rem  = idx - b*(RR*CC*DD);
    int r    = rem / (CC*DD);
    int rem2 = rem - r*(CC*DD);
    int c    = rem2 / DD;
    int i    = rem2 - c*DD;
    const float* w = route_w + ((r*CC + c)*DD + i)*OO;
    const float* v = g_v + (b*CC + c)*OO;
    float acc = 0.f;
#pragma unroll
    for (int o = 0; o < OO; ++o) acc += w[o] * v[o];
    g_WV[idx] = acc;
}

// ---------------- routing pass: softmax weights + G accumulation ----------------
// MODE 1: cw = 0.1 (softmax of zeros), no logit IO
// MODE 2: b = <u_hat,v1> (prev logits are 0), store to g_blog, cw = softmax(b)
// MODE 3: b = g_blog + <u_hat,v2>, cw = softmax(b)
template<int MODE>
__global__ void pass_kernel() {
    const int b = blockIdx.x, r = blockIdx.y;
    const int tid = threadIdx.x;   // 64 threads
    __shared__ float sWV[CC*DD];
    __shared__ float sG[2][CC*DD];

    if (MODE >= 2) {
        for (int j = tid; j < CC*DD; j += 64)
            sWV[j] = g_WV[(b*RR + r)*CC*DD + j];
    }
    __syncthreads();

    float Gp[CC*DD];
#pragma unroll
    for (int j = 0; j < CC*DD; ++j) Gp[j] = 0.f;

    const float* capbase = g_caps + (size_t)(b*RR + r)*P2*DD;

#pragma unroll 1
    for (int pi = 0; pi < 9; ++pi) {
        int p = pi*64 + tid;
        float4 l0 = *(const float4*)(capbase + p*8);
        float4 l1 = *(const float4*)(capbase + p*8 + 4);
        float cv[8] = { l0.x, l0.y, l0.z, l0.w, l1.x, l1.y, l1.z, l1.w };

        float cw[CC];
        if (MODE == 1) {
#pragma unroll
            for (int c = 0; c < CC; ++c) cw[c] = 0.1f;
        } else {
            float bvv[CC];
            long bidx = ((long)b*RR*P2 + (long)r*P2 + p)*CC;
#pragma unroll
            for (int c = 0; c < CC; ++c) {
                float t = 0.f;
#pragma unroll
                for (int i = 0; i < 8; ++i) t += cv[i] * sWV[c*8 + i];
                bvv[c] = ((MODE == 3) ? g_blog[bidx + c] : 0.f) + t;
                if (MODE == 2) g_blog[bidx + c] = bvv[c];
            }
            float mx = bvv[0];
#pragma unroll
            for (int c = 1; c < CC; ++c) mx = fmaxf(mx, bvv[c]);
            float sum = 0.f;
#pragma unroll
            for (int c = 0; c < CC; ++c) { cw[c] = __expf(bvv[c] - mx); sum += cw[c]; }
            float inv = 1.f / sum;
#pragma unroll
            for (int c = 0; c < CC; ++c) cw[c] *= inv;
        }
#pragma unroll
        for (int c = 0; c < CC; ++c)
#pragma unroll
            for (int i = 0; i < 8; ++i) Gp[c*8 + i] += cw[c] * cv[i];
    }

    // reduce Gp over 64 threads
    int wid = tid >> 5, lane = tid & 31;
#pragma unroll
    for (int j = 0; j < CC*DD; ++j) {
        float val = Gp[j];
#pragma unroll
        for (int s = 16; s > 0; s >>= 1) val += __shfl_xor_sync(0xffffffffu, val, s);
        if (lane == 0) sG[wid][j] = val;
    }
    __syncthreads();
    for (int j = tid; j < CC*DD; j += 64)
        g_G[(b*RR + r)*CC*DD + j] = sG[0][j] + sG[1][j];
}

// ---------------- s = G . W ; v = squash(s) ----------------
__global__ void sv_kernel(const float* __restrict__ route_w, float* __restrict__ dout) {
    const int b = blockIdx.x;
    const int tid = threadIdx.x;     // 160 threads = (c,o)
    __shared__ float sGb[RR*CC*DD];  // 2560 floats
    __shared__ float ss[CC*OO];

    for (int j = tid; j < RR*CC*DD; j += CC*OO) sGb[j] = g_G[b*RR*CC*DD + j];
    __syncthreads();

    const int c = tid / OO, o = tid - (tid / OO)*OO;
    float s = 0.f;
#pragma unroll 1
    for (int r = 0; r < RR; ++r) {
#pragma unroll
        for (int i = 0; i < DD; ++i)
            s += sGb[(r*CC + c)*DD + i] * route_w[((r*CC + c)*DD + i)*OO + o];
    }
    ss[tid] = s;
    __syncthreads();
    float norm = 0.f;
#pragma unroll
    for (int oo = 0; oo < OO; ++oo) { float t = ss[c*OO + oo]; norm += t*t; }
    float scale = norm / ((1.f + norm) * sqrtf(norm + 1e-8f));
    float val = scale * s;
    g_v[b*CC*OO + tid] = val;
    if (dout) dout[b*CC*OO + tid] = val;
}

// ---------------- launcher ----------------
extern "C" void kernel_launch(void* const* d_in, const int* in_sizes, int n_in,
                              void* d_out, int out_size)
{
    // metadata order == setup_inputs order
    const float* x  = (const float*)d_in[0];   // [32,3,64,64]
    const float* w1 = (const float*)d_in[1];   // [256,3,9,9]
    const float* b1 = (const float*)d_in[2];   // [256]
    const float* w2 = (const float*)d_in[3];   // [256,256,9,9]
    const float* b2 = (const float*)d_in[4];   // [256]
    const float* rw = (const float*)d_in[5];   // [32,10,8,16]
    float* out = (float*)d_out;

    // weight transposes (K-major)
    wt1_kernel<<<(K1PAD*MCH + 255)/256, 256>>>(w1);
    wt2_kernel<<<K2, 256>>>(w2);

    // conv1 (implicit GEMM, relu+bias fused) -> g_h1
    gemm_kernel<1><<<dim3(N1/128, 2), 256>>>(x, b1);
    // conv2 (implicit GEMM, bias fused, caps layout) -> g_caps
    gemm_kernel<2><<<dim3(N2/128, 2), 256>>>(nullptr, b2);
    // squash primary caps in place
    squash_caps_kernel<<<(NB*RR*P2 + 255)/256, 256>>>();

    // routing iteration 1 (uniform weights)
    pass_kernel<1><<<dim3(NB, RR), 64>>>();
    sv_kernel<<<NB, CC*OO>>>(rw, nullptr);          // v1
    // routing iteration 2
    wv_kernel<<<(NB*RR*CC*DD + 127)/128, 128>>>(rw);
    pass_kernel<2><<<dim3(NB, RR), 64>>>();
    sv_kernel<<<NB, CC*OO>>>(rw, nullptr);          // v2
    // routing iteration 3 (final)
    wv_kernel<<<(NB*RR*CC*DD + 127)/128, 128>>>(rw);
    pass_kernel<3><<<dim3(NB, RR), 64>>>();
    sv_kernel<<<NB, CC*OO>>>(rw, out);              // v3 -> d_out
    (void)out_size;
}

// round 10
// speedup vs baseline: 2.4073x; 2.2405x over previous
#include <cuda_runtime.h>
#include <cuda_bf16.h>

typedef unsigned long long u64;

// ---------------- packed f32x2 helpers ----------------
__device__ __forceinline__ u64 pack2(float x) {
    u64 r; unsigned u = __float_as_uint(x);
    asm("mov.b64 %0, {%1, %2};" : "=l"(r) : "r"(u), "r"(u));
    return r;
}
__device__ __forceinline__ void fma2(u64 &acc, u64 a, u64 b) {
    asm("fma.rn.f32x2 %0, %1, %2, %0;" : "+l"(acc) : "l"(a), "l"(b));
}
__device__ __forceinline__ float2 unpack2(u64 v) {
    unsigned lo, hi;
    asm("mov.b64 {%0, %1}, %2;" : "=r"(lo), "=r"(hi) : "l"(v));
    return make_float2(__uint_as_float(lo), __uint_as_float(hi));
}

// ---------------- cp.async helpers ----------------
__device__ __forceinline__ unsigned smem_u32(const void* p) {
    return (unsigned)__cvta_generic_to_shared(p);
}
__device__ __forceinline__ void cp4(unsigned dst, const float* src, int srcsize) {
    asm volatile("cp.async.ca.shared.global [%0], [%1], 4, %2;"
                 :: "r"(dst), "l"(src), "r"(srcsize));
}
__device__ __forceinline__ void cp4u(unsigned dst, const float* src) {
    asm volatile("cp.async.ca.shared.global [%0], [%1], 4;"
                 :: "r"(dst), "l"(src));
}
__device__ __forceinline__ void cp16(unsigned dst, const void* src) {
    asm volatile("cp.async.cg.shared.global [%0], [%1], 16;"
                 :: "r"(dst), "l"(src));
}
__device__ __forceinline__ void cp_commit() {
    asm volatile("cp.async.commit_group;");
}
template<int N>
__device__ __forceinline__ void cp_wait() {
    asm volatile("cp.async.wait_group %0;" :: "n"(N));
}

// ---------------- mma.sync helpers (baseline PTX, no 'a' features) ----------------
__device__ __forceinline__ void ldm4(unsigned r[4], unsigned addr) {
    asm volatile("ldmatrix.sync.aligned.m8n8.x4.shared.b16 {%0,%1,%2,%3}, [%4];"
                 : "=r"(r[0]), "=r"(r[1]), "=r"(r[2]), "=r"(r[3]) : "r"(addr));
}
__device__ __forceinline__ void mma16816(float c[4], const unsigned a[4],
                                         unsigned b0, unsigned b1) {
    asm volatile("mma.sync.aligned.m16n8k16.row.col.f32.bf16.bf16.f32 "
                 "{%0,%1,%2,%3}, {%4,%5,%6,%7}, {%8,%9}, {%0,%1,%2,%3};"
                 : "+f"(c[0]), "+f"(c[1]), "+f"(c[2]), "+f"(c[3])
                 : "r"(a[0]), "r"(a[1]), "r"(a[2]), "r"(a[3]), "r"(b0), "r"(b1));
}

// ---------------- problem constants ----------------
#define NB    32
#define OH1   56
#define NPIX1 (OH1*OH1)   // 3136
#define N1    (NB*NPIX1)  // 100352
#define K1    243
#define K1PAD 248
#define OH2   24
#define P2    (OH2*OH2)   // 576
#define N2    (NB*P2)     // 18432
#define K2    20736
#define MCH   256
#define RR    32
#define DD    8
#define CC    10
#define OO    16

// conv2 mma tiling
#define KCH    32
#define NCH    (K2/KCH)     // 648
#define OFF_ALO 10240       // bytes; A tile = 128 rows x 80B
#define OFF_BHI 20480
#define OFF_BLO 30720
#define STAGE_B 40960
#define CONV2_SMEM (2*STAGE_B)   // 80 KB

// ---------------- scratch (static device memory only) ----------------
__device__ __align__(16) unsigned g_h1p[NB*MCH*NPIX1];   // conv1 out packed (bf16hi | bf16lo<<16)
__device__ __align__(16) float    g_caps[NB*RR*P2*DD];
__device__ __align__(16) float    g_w1t[K1PAD*MCH];
__device__ __align__(16) unsigned g_w2img[NCH*2*256*16]; // [chunk][plane][ch][16 u32 = 32 bf16]
__device__ __align__(16) float    g_WV[NB*RR*CC*DD];
__device__ __align__(16) float    g_G[NB*RR*CC*DD];
__device__ __align__(16) float    g_v[NB*CC*OO];
__device__ __align__(16) float    g_blog[NB*RR*P2*CC];

// ---------------- bf16 split pack ----------------
__device__ __forceinline__ unsigned pack_split(float v) {
    __nv_bfloat16 h = __float2bfloat16(v);
    float hf = __bfloat162float(h);
    __nv_bfloat16 l = __float2bfloat16(v - hf);
    return (unsigned)__bfloat16_as_ushort(h) | ((unsigned)__bfloat16_as_ushort(l) << 16);
}

// ---------------- conv1 weight transpose ----------------
__global__ void wt1_kernel(const float* __restrict__ w) {
    int idx = blockIdx.x * 256 + threadIdx.x;
    if (idx >= K1PAD*MCH) return;
    int k = idx >> 8, m = idx & 255;
    float v = 0.f;
    if (k < K1) v = w[m*K1 + k];
    g_w1t[idx] = v;
}

// ---------------- conv2 weight split into linear image ----------------
__global__ void wsplit_kernel(const float* __restrict__ w2) {
    int t  = blockIdx.x * 256 + threadIdx.x;  // 256ch * K2/2 pairs
    int ch = t / (K2/2);
    int kp = t - ch*(K2/2);
    int k  = 2*kp;
    unsigned p0 = pack_split(w2[ch*K2 + k]);
    unsigned p1 = pack_split(w2[ch*K2 + k + 1]);
    unsigned hi01 = __byte_perm(p0, p1, 0x5410);
    unsigned lo01 = __byte_perm(p0, p1, 0x7632);
    int chunk = k >> 5, kk = k & 31;
    g_w2img[((chunk*2 + 0)*256 + ch)*16 + (kk >> 1)] = hi01;
    g_w2img[((chunk*2 + 1)*256 + ch)*16 + (kk >> 1)] = lo01;
}

// ---------------- conv1: implicit GEMM (f32x2, 3-stage cp.async) ----------------
__global__ __launch_bounds__(256, 2)
void conv1_kernel(const float* __restrict__ Xin, const float* __restrict__ bias)
{
    constexpr int NT = K1PAD / 8;
    __shared__ __align__(16) float As[3][8][128];
    __shared__ __align__(16) float Bs[3][8][128];

    const int tid = threadIdx.x;
    const int tx  = tid & 15;
    const int ty  = tid >> 4;
    const int n0  = blockIdx.x * 128;
    const int m0  = blockIdx.y * 128;

    u64 acc[8][4];
#pragma unroll
    for (int i = 0; i < 8; ++i)
#pragma unroll
        for (int j = 0; j < 4; ++j) acc[i][j] = 0ull;

    const int ldk = tid >> 7;
    const int ldn = tid & 127;

    const int ng = n0 + ldn;
    int base;
    {
        int b   = ng / NPIX1;
        int rem = ng - b*NPIX1;
        int oy  = rem / OH1;
        int ox  = rem - oy*OH1;
        base = b*3*4096 + oy*64 + ox;
    }
    int off[4], kx[4], ky[4];
#pragma unroll
    for (int i = 0; i < 4; ++i) {
        int k0i = ldk + 2*i;
        off[i] = base + k0i; kx[i] = k0i; ky[i] = 0;
    }
    const float* aA = g_w1t + ldk*MCH + m0 + ldn;
    int kpref = 0;

    auto PREFETCH = [&](int s) {
#pragma unroll
        for (int i = 0; i < 4; ++i) {
            int k = ldk + 2*i;
            cp4u(smem_u32(&As[s][k][ldn]), aA + i*2*MCH);
            int ok = (kpref + k < K1);
            cp4(smem_u32(&Bs[s][k][ldn]), Xin + (ok ? off[i] : 0), ok ? 4 : 0);
            kx[i] += 8; off[i] += 8;
            if (kx[i] >= 9) {
                kx[i] -= 9; off[i] += 64 - 9;
                if (++ky[i] >= 9) { ky[i] -= 9; off[i] += 4096 - 9*64; }
            }
        }
        aA += 8*MCH;
        kpref += 8;
        cp_commit();
    };

    PREFETCH(0);
    PREFETCH(1);

#pragma unroll 1
    for (int it = 0; it < NT; ++it) {
        cp_wait<1>();
        __syncthreads();
        if (it + 2 < NT) PREFETCH((it + 2) % 3);
        else             cp_commit();
        const int s = it % 3;
#pragma unroll
        for (int kk = 0; kk < 8; ++kk) {
            union F4U { float4 f; u64 u[2]; };
            F4U b0, b1, a0, a1;
            b0.f = *(const float4*)&Bs[s][kk][tx*4];
            b1.f = *(const float4*)&Bs[s][kk][64 + tx*4];
            a0.f = *(const float4*)&As[s][kk][ty*4];
            a1.f = *(const float4*)&As[s][kk][64 + ty*4];
            u64 bb[4] = { b0.u[0], b0.u[1], b1.u[0], b1.u[1] };
            float av[8] = { a0.f.x, a0.f.y, a0.f.z, a0.f.w,
                            a1.f.x, a1.f.y, a1.f.z, a1.f.w };
#pragma unroll
            for (int i = 0; i < 8; ++i) {
                u64 a2 = pack2(av[i]);
#pragma unroll
                for (int j = 0; j < 4; ++j) fma2(acc[i][j], a2, bb[j]);
            }
        }
    }

    // epilogue: bias + relu + bf16-split pack
#pragma unroll
    for (int i = 0; i < 8; ++i) {
        int m = m0 + ((i < 4) ? (ty*4 + i) : (64 + ty*4 + (i - 4)));
        float bv = bias[m];
#pragma unroll
        for (int j = 0; j < 4; ++j) {
            float2 v2 = unpack2(acc[i][j]);
            int ncol = n0 + ((j < 2) ? (tx*4 + 2*j) : (64 + tx*4 + 2*(j - 2)));
#pragma unroll
            for (int e = 0; e < 2; ++e) {
                int n = ncol + e;
                float val = ((e == 0) ? v2.x : v2.y) + bv;
                val = val > 0.f ? val : 0.f;
                int b = n / NPIX1, rem = n - b*NPIX1;
                g_h1p[(b*MCH + m)*NPIX1 + rem] = pack_split(val);
            }
        }
    }
}

// ---------------- conv2: bf16-split implicit GEMM on mma.sync ----------------
// D[128 spatial][128 ch] per CTA. 8 warps (4m x 2n), warp tile 32x64.
__global__ __launch_bounds__(256, 2)
void conv2_mma(const float* __restrict__ bias)
{
    extern __shared__ __align__(128) char smraw[];
    const unsigned sb = smem_u32(smraw);
    const int tid  = threadIdx.x;
    const int lane = tid & 31;
    const int wid  = tid >> 5;
    const int wm   = wid & 3;      // m-warp 0..3 (32 rows each)
    const int wn   = wid >> 2;     // n-warp 0..1 (64 ch each)
    const int m0   = blockIdx.x * 128;
    const int ch0  = blockIdx.y * 128;

    // ---- fill-state: this thread fills k-pair p for rows rbase+16*i ----
    const int p     = tid & 15;
    const int rbase = tid >> 4;
    int ic, ky, kx;
    { int k0 = 2*p; ic = 0; ky = k0/9; kx = k0 - 9*ky; }
    int naddr[8];
#pragma unroll
    for (int i = 0; i < 8; ++i) {
        int nsp = m0 + rbase + 16*i;
        int b = nsp / P2, rem = nsp - b*P2;
        int oy = rem / OH2, ox = rem - oy*OH2;
        naddr[i] = b*(MCH*NPIX1) + oy*(2*OH1) + ox*2;
    }

    float acc[2][8][4];
#pragma unroll
    for (int mt = 0; mt < 2; ++mt)
#pragma unroll
        for (int nt = 0; nt < 8; ++nt)
#pragma unroll
            for (int q = 0; q < 4; ++q) acc[mt][nt][q] = 0.f;

    // ldmatrix lane address components
    const int arow = (lane & 7) + ((lane >> 3) & 1)*8;
    const int acol = ((lane >> 4) & 1)*8;
    const int brow = (lane & 7) + ((lane >> 4) & 1)*8;
    const int bcol = ((lane >> 3) & 1)*8;
    const unsigned aoff = (unsigned)((wm*32 + arow)*80 + acol*2);
    const unsigned boff = (unsigned)(OFF_BHI + (wn*64 + brow)*80 + bcol*2);

    auto FILL = [&](int c, unsigned st) {
        // B: weights via cp.async from linear pre-split image
#pragma unroll
        for (int it = 0; it < 4; ++it) {
            int g     = tid + 256*it;
            int plane = g >> 9;
            int chrow = (g >> 2) & 127;
            int j     = g & 3;
            const unsigned* src = g_w2img + (((c*2 + plane)*256) + ch0 + chrow)*16 + j*4;
            unsigned dst = st + (plane ? OFF_BLO : OFF_BHI) + (unsigned)chrow*80 + j*16;
            cp16(dst, src);
        }
        cp_commit();
        // A: im2col from packed h1, split hi/lo
        int ka  = ic*NPIX1 + ky*OH1 + kx;
        int ka2 = ka + ((kx == 8) ? ((ky == 8) ? (NPIX1 - 8*OH1 - 8) : (OH1 - 8)) : 1);
#pragma unroll
        for (int i = 0; i < 8; ++i) {
            unsigned w0 = g_h1p[naddr[i] + ka];
            unsigned w1 = g_h1p[naddr[i] + ka2];
            unsigned hi01 = __byte_perm(w0, w1, 0x5410);
            unsigned lo01 = __byte_perm(w0, w1, 0x7632);
            unsigned d = st + (unsigned)(rbase + 16*i)*80 + 4u*p;
            asm volatile("st.shared.b32 [%0], %1;" :: "r"(d), "r"(hi01) : "memory");
            asm volatile("st.shared.b32 [%0], %1;" :: "r"(d + OFF_ALO), "r"(lo01) : "memory");
        }
        // advance k by 32 (= 3*9 + 5)
        kx += 5; ky += 3;
        if (kx >= 9) { kx -= 9; ++ky; }
        if (ky >= 9) { ky -= 9; ++ic; }
    };

    FILL(0, sb);

#pragma unroll 1
    for (int c = 0; c < NCH; ++c) {
        cp_wait<0>();          // B(c) landed (each thread waits its own group)
        __syncthreads();       // A(c)/B(c) visible; all warps done with mma(c-1)
        if (c + 1 < NCH) FILL(c + 1, sb + (unsigned)((c + 1) & 1)*STAGE_B);
        const unsigned st = sb + (unsigned)(c & 1)*STAGE_B;

#pragma unroll
        for (int kh = 0; kh < 2; ++kh) {
            const unsigned ka_ = st + aoff + kh*32;
            const unsigned kb_ = st + boff + kh*32;
            unsigned ah[2][4], al[2][4], bb[4][4];
            ldm4(ah[0], ka_);
            ldm4(ah[1], ka_ + 1280);
            ldm4(al[0], ka_ + OFF_ALO);
            ldm4(al[1], ka_ + OFF_ALO + 1280);
#pragma unroll
            for (int j = 0; j < 4; ++j) ldm4(bb[j], kb_ + j*1280);
#pragma unroll
            for (int mt = 0; mt < 2; ++mt)
#pragma unroll
                for (int j = 0; j < 4; ++j) {
                    mma16816(acc[mt][2*j],   ah[mt], bb[j][0], bb[j][1]);
                    mma16816(acc[mt][2*j+1], ah[mt], bb[j][2], bb[j][3]);
                    mma16816(acc[mt][2*j],   al[mt], bb[j][0], bb[j][1]);
                    mma16816(acc[mt][2*j+1], al[mt], bb[j][2], bb[j][3]);
                }
#pragma unroll
            for (int j = 0; j < 4; ++j) ldm4(bb[j], kb_ + (OFF_BLO - OFF_BHI) + j*1280);
#pragma unroll
            for (int mt = 0; mt < 2; ++mt)
#pragma unroll
                for (int j = 0; j < 4; ++j) {
                    mma16816(acc[mt][2*j],   ah[mt], bb[j][0], bb[j][1]);
                    mma16816(acc[mt][2*j+1], ah[mt], bb[j][2], bb[j][3]);
                }
        }
    }

    // ---- epilogue: acc + bias -> caps layout ----
#pragma unroll
    for (int mt = 0; mt < 2; ++mt) {
        int rowA = m0 + wm*32 + mt*16 + (lane >> 2);
#pragma unroll
        for (int half = 0; half < 2; ++half) {
            int nsp = rowA + half*8;
            int b = nsp / P2, pp = nsp - b*P2;
            long obase = ((long)(b*RR))*P2 + pp;
#pragma unroll
            for (int nt = 0; nt < 8; ++nt) {
                int chb = ch0 + wn*64 + nt*8 + (lane & 3)*2;
#pragma unroll
                for (int e = 0; e < 2; ++e) {
                    int ch = chb + e;
                    float v = acc[mt][nt][half*2 + e] + bias[ch];
                    int rr = ch >> 3, dd = ch & 7;
                    g_caps[(obase + (long)rr*P2)*DD + dd] = v;
                }
            }
        }
    }
}

// ---------------- squash primary capsules (in place) ----------------
__global__ void squash_caps_kernel() {
    int v = blockIdx.x * 256 + threadIdx.x;
    if (v >= NB*RR*P2) return;
    float4 lo = *(float4*)&g_caps[v*8];
    float4 hi = *(float4*)&g_caps[v*8 + 4];
    float norm = lo.x*lo.x + lo.y*lo.y + lo.z*lo.z + lo.w*lo.w
               + hi.x*hi.x + hi.y*hi.y + hi.z*hi.z + hi.w*hi.w;
    float scale = norm / ((1.f + norm) * sqrtf(norm + 1e-8f));
    lo.x *= scale; lo.y *= scale; lo.z *= scale; lo.w *= scale;
    hi.x *= scale; hi.y *= scale; hi.z *= scale; hi.w *= scale;
    *(float4*)&g_caps[v*8]     = lo;
    *(float4*)&g_caps[v*8 + 4] = hi;
}

// ---------------- WV[b,r,c,i] = sum_o route_w[r,c,i,o] * v[b,c,o] ----------------
__global__ void wv_kernel(const float* __restrict__ route_w) {
    int idx = blockIdx.x * 128 + threadIdx.x;
    if (idx >= NB*RR*CC*DD) return;
    int b    = idx / (RR*CC*DD);
    int rem  = idx - b*(RR*CC*DD);
    int r    = rem / (CC*DD);
    int rem2 = rem - r*(CC*DD);
    int c    = rem2 / DD;
    int i    = rem2 - c*DD;
    const float* w = route_w + ((r*CC + c)*DD + i)*OO;
    const float* v = g_v + (b*CC + c)*OO;
    float acc = 0.f;
#pragma unroll
    for (int o = 0; o < OO; ++o) acc += w[o] * v[o];
    g_WV[idx] = acc;
}

// ---------------- routing pass ----------------
template<int MODE>
__global__ void pass_kernel() {
    const int b = blockIdx.x, r = blockIdx.y;
    const int tid = threadIdx.x;   // 64 threads
    __shared__ float sWV[CC*DD];
    __shared__ float sG[2][CC*DD];

    if (MODE >= 2) {
        for (int j = tid; j < CC*DD; j += 64)
            sWV[j] = g_WV[(b*RR + r)*CC*DD + j];
    }
    __syncthreads();

    float Gp[CC*DD];
#pragma unroll
    for (int j = 0; j < CC*DD; ++j) Gp[j] = 0.f;

    const float* capbase = g_caps + (size_t)(b*RR + r)*P2*DD;

#pragma unroll 1
    for (int pi = 0; pi < 9; ++pi) {
        int p = pi*64 + tid;
        float4 l0 = *(const float4*)(capbase + p*8);
        float4 l1 = *(const float4*)(capbase + p*8 + 4);
        float cv[8] = { l0.x, l0.y, l0.z, l0.w, l1.x, l1.y, l1.z, l1.w };

        float cw[CC];
        if (MODE == 1) {
#pragma unroll
            for (int c = 0; c < CC; ++c) cw[c] = 0.1f;
        } else {
            float bvv[CC];
            long bidx = ((long)b*RR*P2 + (long)r*P2 + p)*CC;
#pragma unroll
            for (int c = 0; c < CC; ++c) {
                float t = 0.f;
#pragma unroll
                for (int i = 0; i < 8; ++i) t += cv[i] * sWV[c*8 + i];
                bvv[c] = ((MODE == 3) ? g_blog[bidx + c] : 0.f) + t;
                if (MODE == 2) g_blog[bidx + c] = bvv[c];
            }
            float mx = bvv[0];
#pragma unroll
            for (int c = 1; c < CC; ++c) mx = fmaxf(mx, bvv[c]);
            float sum = 0.f;
#pragma unroll
            for (int c = 0; c < CC; ++c) { cw[c] = __expf(bvv[c] - mx); sum += cw[c]; }
            float inv = 1.f / sum;
#pragma unroll
            for (int c = 0; c < CC; ++c) cw[c] *= inv;
        }
#pragma unroll
        for (int c = 0; c < CC; ++c)
#pragma unroll
            for (int i = 0; i < 8; ++i) Gp[c*8 + i] += cw[c] * cv[i];
    }

    int wid2 = tid >> 5, lane = tid & 31;
#pragma unroll
    for (int j = 0; j < CC*DD; ++j) {
        float val = Gp[j];
#pragma unroll
        for (int s = 16; s > 0; s >>= 1) val += __shfl_xor_sync(0xffffffffu, val, s);
        if (lane == 0) sG[wid2][j] = val;
    }
    __syncthreads();
    for (int j = tid; j < CC*DD; j += 64)
        g_G[(b*RR + r)*CC*DD + j] = sG[0][j] + sG[1][j];
}

// ---------------- s = G . W ; v = squash(s) ----------------
__global__ void sv_kernel(const float* __restrict__ route_w, float* __restrict__ dout) {
    const int b = blockIdx.x;
    const int tid = threadIdx.x;     // 160 threads = (c,o)
    __shared__ float sGb[RR*CC*DD];
    __shared__ float ss[CC*OO];

    for (int j = tid; j < RR*CC*DD; j += CC*OO) sGb[j] = g_G[b*RR*CC*DD + j];
    __syncthreads();

    const int c = tid / OO, o = tid - (tid / OO)*OO;
    float s = 0.f;
#pragma unroll 1
    for (int r = 0; r < RR; ++r) {
#pragma unroll
        for (int i = 0; i < DD; ++i)
            s += sGb[(r*CC + c)*DD + i] * route_w[((r*CC + c)*DD + i)*OO + o];
    }
    ss[tid] = s;
    __syncthreads();
    float norm = 0.f;
#pragma unroll
    for (int oo = 0; oo < OO; ++oo) { float t = ss[c*OO + oo]; norm += t*t; }
    float scale = norm / ((1.f + norm) * sqrtf(norm + 1e-8f));
    float val = scale * s;
    g_v[b*CC*OO + tid] = val;
    if (dout) dout[b*CC*OO + tid] = val;
}

// ---------------- launcher ----------------
extern "C" void kernel_launch(void* const* d_in, const int* in_sizes, int n_in,
                              void* d_out, int out_size)
{
    const float* x  = (const float*)d_in[0];   // [32,3,64,64]
    const float* w1 = (const float*)d_in[1];   // [256,3,9,9]
    const float* b1 = (const float*)d_in[2];   // [256]
    const float* w2 = (const float*)d_in[3];   // [256,256,9,9]
    const float* b2 = (const float*)d_in[4];   // [256]
    const float* rw = (const float*)d_in[5];   // [32,10,8,16]
    float* out = (float*)d_out;

    static int smem_set = 0;
    if (!smem_set) {
        cudaFuncSetAttribute(conv2_mma,
                             cudaFuncAttributeMaxDynamicSharedMemorySize, CONV2_SMEM);
        smem_set = 1;
    }

    // weight prep
    wt1_kernel<<<(K1PAD*MCH + 255)/256, 256>>>(w1);
    wsplit_kernel<<<K2/2, 256>>>(w2);

    // conv1 -> g_h1p (packed bf16-split)
    conv1_kernel<<<dim3(N1/128, 2), 256>>>(x, b1);
    // conv2 -> g_caps (mma.sync tensor cores)
    conv2_mma<<<dim3(N2/128, 2), 256, CONV2_SMEM>>>(b2);
    // squash primary caps
    squash_caps_kernel<<<(NB*RR*P2 + 255)/256, 256>>>();

    // routing iteration 1
    pass_kernel<1><<<dim3(NB, RR), 64>>>();
    sv_kernel<<<NB, CC*OO>>>(rw, nullptr);
    // routing iteration 2
    wv_kernel<<<(NB*RR*CC*DD + 127)/128, 128>>>(rw);
    pass_kernel<2><<<dim3(NB, RR), 64>>>();
    sv_kernel<<<NB, CC*OO>>>(rw, nullptr);
    // routing iteration 3 (final)
    wv_kernel<<<(NB*RR*CC*DD + 127)/128, 128>>>(rw);
    pass_kernel<3><<<dim3(NB, RR), 64>>>();
    sv_kernel<<<NB, CC*OO>>>(rw, out);
    (void)out_size;
}

// round 11
// speedup vs baseline: 2.5334x; 1.0524x over previous
#include <cuda_runtime.h>
#include <cuda_bf16.h>

typedef unsigned long long u64;

// ---------------- packed f32x2 helpers ----------------
__device__ __forceinline__ u64 pack2(float x) {
    u64 r; unsigned u = __float_as_uint(x);
    asm("mov.b64 %0, {%1, %2};" : "=l"(r) : "r"(u), "r"(u));
    return r;
}
__device__ __forceinline__ void fma2(u64 &acc, u64 a, u64 b) {
    asm("fma.rn.f32x2 %0, %1, %2, %0;" : "+l"(acc) : "l"(a), "l"(b));
}
__device__ __forceinline__ float2 unpack2(u64 v) {
    unsigned lo, hi;
    asm("mov.b64 {%0, %1}, %2;" : "=r"(lo), "=r"(hi) : "l"(v));
    return make_float2(__uint_as_float(lo), __uint_as_float(hi));
}

// ---------------- cp.async helpers ----------------
__device__ __forceinline__ unsigned smem_u32(const void* p) {
    return (unsigned)__cvta_generic_to_shared(p);
}
__device__ __forceinline__ void cp4(unsigned dst, const float* src, int srcsize) {
    asm volatile("cp.async.ca.shared.global [%0], [%1], 4, %2;"
                 :: "r"(dst), "l"(src), "r"(srcsize));
}
__device__ __forceinline__ void cp4u(unsigned dst, const float* src) {
    asm volatile("cp.async.ca.shared.global [%0], [%1], 4;"
                 :: "r"(dst), "l"(src));
}
__device__ __forceinline__ void cp16(unsigned dst, const void* src) {
    asm volatile("cp.async.cg.shared.global [%0], [%1], 16;"
                 :: "r"(dst), "l"(src));
}
__device__ __forceinline__ void cp_commit() {
    asm volatile("cp.async.commit_group;");
}
template<int N>
__device__ __forceinline__ void cp_wait() {
    asm volatile("cp.async.wait_group %0;" :: "n"(N));
}

// ---------------- mma.sync helpers (baseline PTX, no 'a' features) ----------------
__device__ __forceinline__ void ldm4(unsigned r[4], unsigned addr) {
    asm volatile("ldmatrix.sync.aligned.m8n8.x4.shared.b16 {%0,%1,%2,%3}, [%4];"
                 : "=r"(r[0]), "=r"(r[1]), "=r"(r[2]), "=r"(r[3]) : "r"(addr));
}
__device__ __forceinline__ void mma16816(float c[4], const unsigned a[4],
                                         unsigned b0, unsigned b1) {
    asm volatile("mma.sync.aligned.m16n8k16.row.col.f32.bf16.bf16.f32 "
                 "{%0,%1,%2,%3}, {%4,%5,%6,%7}, {%8,%9}, {%0,%1,%2,%3};"
                 : "+f"(c[0]), "+f"(c[1]), "+f"(c[2]), "+f"(c[3])
                 : "r"(a[0]), "r"(a[1]), "r"(a[2]), "r"(a[3]), "r"(b0), "r"(b1));
}

// ---------------- problem constants ----------------
#define NB    32
#define OH1   56
#define NPIX1 (OH1*OH1)   // 3136
#define N1    (NB*NPIX1)  // 100352
#define K1    243
#define K1PAD 248
#define OH2   24
#define P2    (OH2*OH2)   // 576
#define N2    (NB*P2)     // 18432
#define K2    20736
#define MCH   256
#define RR    32
#define DD    8
#define CC    10
#define OO    16

// conv2 mma tiling
#define KCH    32
#define NCH    (K2/KCH)     // 648
#define OFF_ALO 10240       // bytes; A tile = 128 rows x 80B
#define OFF_BHI 20480
#define OFF_BLO 30720
#define STAGE_B 40960
#define CONV2_SMEM (2*STAGE_B)   // 80 KB

// ---------------- scratch (static device memory only) ----------------
__device__ __align__(16) unsigned g_h1p[NB*MCH*NPIX1];   // conv1 out packed (bf16hi | bf16lo<<16)
__device__ __align__(16) float    g_caps[NB*RR*P2*DD];
__device__ __align__(16) float    g_w1t[K1PAD*MCH];
__device__ __align__(16) unsigned g_w2img[NCH*2*256*16]; // [chunk][plane][ch][16 u32 = 32 bf16]
__device__ __align__(16) float    g_WV[NB*RR*CC*DD];
__device__ __align__(16) float    g_G[NB*RR*CC*DD];
__device__ __align__(16) float    g_v[NB*CC*OO];
__device__ __align__(16) float    g_blog[NB*RR*P2*CC];

// ---------------- bf16 split pack ----------------
__device__ __forceinline__ unsigned pack_split(float v) {
    __nv_bfloat16 h = __float2bfloat16(v);
    float hf = __bfloat162float(h);
    __nv_bfloat16 l = __float2bfloat16(v - hf);
    return (unsigned)__bfloat16_as_ushort(h) | ((unsigned)__bfloat16_as_ushort(l) << 16);
}

// ---------------- conv1 weight transpose ----------------
__global__ void wt1_kernel(const float* __restrict__ w) {
    int idx = blockIdx.x * 256 + threadIdx.x;
    if (idx >= K1PAD*MCH) return;
    int k = idx >> 8, m = idx & 255;
    float v = 0.f;
    if (k < K1) v = w[m*K1 + k];
    g_w1t[idx] = v;
}

// ---------------- conv2 weight split into linear image ----------------
__global__ void wsplit_kernel(const float* __restrict__ w2) {
    int t  = blockIdx.x * 256 + threadIdx.x;  // 256ch * K2/2 pairs
    int ch = t / (K2/2);
    int kp = t - ch*(K2/2);
    int k  = 2*kp;
    unsigned p0 = pack_split(w2[ch*K2 + k]);
    unsigned p1 = pack_split(w2[ch*K2 + k + 1]);
    unsigned hi01 = __byte_perm(p0, p1, 0x5410);
    unsigned lo01 = __byte_perm(p0, p1, 0x7632);
    int chunk = k >> 5, kk = k & 31;
    g_w2img[((chunk*2 + 0)*256 + ch)*16 + (kk >> 1)] = hi01;
    g_w2img[((chunk*2 + 1)*256 + ch)*16 + (kk >> 1)] = lo01;
}

// ---------------- conv1: implicit GEMM (f32x2, 3-stage cp.async) ----------------
__global__ __launch_bounds__(256, 2)
void conv1_kernel(const float* __restrict__ Xin, const float* __restrict__ bias)
{
    constexpr int NT = K1PAD / 8;
    __shared__ __align__(16) float As[3][8][128];
    __shared__ __align__(16) float Bs[3][8][128];

    const int tid = threadIdx.x;
    const int tx  = tid & 15;
    const int ty  = tid >> 4;
    const int n0  = blockIdx.x * 128;
    const int m0  = blockIdx.y * 128;

    u64 acc[8][4];
#pragma unroll
    for (int i = 0; i < 8; ++i)
#pragma unroll
        for (int j = 0; j < 4; ++j) acc[i][j] = 0ull;

    const int ldk = tid >> 7;
    const int ldn = tid & 127;

    const int ng = n0 + ldn;
    int base;
    {
        int b   = ng / NPIX1;
        int rem = ng - b*NPIX1;
        int oy  = rem / OH1;
        int ox  = rem - oy*OH1;
        base = b*3*4096 + oy*64 + ox;
    }
    int off[4], kx[4], ky[4];
#pragma unroll
    for (int i = 0; i < 4; ++i) {
        int k0i = ldk + 2*i;
        off[i] = base + k0i; kx[i] = k0i; ky[i] = 0;
    }
    const float* aA = g_w1t + ldk*MCH + m0 + ldn;
    int kpref = 0;

    auto PREFETCH = [&](int s) {
#pragma unroll
        for (int i = 0; i < 4; ++i) {
            int k = ldk + 2*i;
            cp4u(smem_u32(&As[s][k][ldn]), aA + i*2*MCH);
            int ok = (kpref + k < K1);
            cp4(smem_u32(&Bs[s][k][ldn]), Xin + (ok ? off[i] : 0), ok ? 4 : 0);
            kx[i] += 8; off[i] += 8;
            if (kx[i] >= 9) {
                kx[i] -= 9; off[i] += 64 - 9;
                if (++ky[i] >= 9) { ky[i] -= 9; off[i] += 4096 - 9*64; }
            }
        }
        aA += 8*MCH;
        kpref += 8;
        cp_commit();
    };

    PREFETCH(0);
    PREFETCH(1);

#pragma unroll 1
    for (int it = 0; it < NT; ++it) {
        cp_wait<1>();
        __syncthreads();
        if (it + 2 < NT) PREFETCH((it + 2) % 3);
        else             cp_commit();
        const int s = it % 3;
#pragma unroll
        for (int kk = 0; kk < 8; ++kk) {
            union F4U { float4 f; u64 u[2]; };
            F4U b0, b1, a0, a1;
            b0.f = *(const float4*)&Bs[s][kk][tx*4];
            b1.f = *(const float4*)&Bs[s][kk][64 + tx*4];
            a0.f = *(const float4*)&As[s][kk][ty*4];
            a1.f = *(const float4*)&As[s][kk][64 + ty*4];
            u64 bb[4] = { b0.u[0], b0.u[1], b1.u[0], b1.u[1] };
            float av[8] = { a0.f.x, a0.f.y, a0.f.z, a0.f.w,
                            a1.f.x, a1.f.y, a1.f.z, a1.f.w };
#pragma unroll
            for (int i = 0; i < 8; ++i) {
                u64 a2 = pack2(av[i]);
#pragma unroll
                for (int j = 0; j < 4; ++j) fma2(acc[i][j], a2, bb[j]);
            }
        }
    }

    // epilogue: bias + relu + bf16-split pack
#pragma unroll
    for (int i = 0; i < 8; ++i) {
        int m = m0 + ((i < 4) ? (ty*4 + i) : (64 + ty*4 + (i - 4)));
        float bv = bias[m];
#pragma unroll
        for (int j = 0; j < 4; ++j) {
            float2 v2 = unpack2(acc[i][j]);
            int ncol = n0 + ((j < 2) ? (tx*4 + 2*j) : (64 + tx*4 + 2*(j - 2)));
#pragma unroll
            for (int e = 0; e < 2; ++e) {
                int n = ncol + e;
                float val = ((e == 0) ? v2.x : v2.y) + bv;
                val = val > 0.f ? val : 0.f;
                int b = n / NPIX1, rem = n - b*NPIX1;
                g_h1p[(b*MCH + m)*NPIX1 + rem] = pack_split(val);
            }
        }
    }
}

// ---------------- conv2: bf16-split implicit GEMM on mma.sync ----------------
// D[128 spatial][128 ch] per CTA. 8 warps (4m x 2n), warp tile 32x64.
// A-fill LDGs are prefetched into registers BEFORE the MMA section and
// stored to SMEM after it, hiding the global-load latency under tensor work.
__global__ __launch_bounds__(256, 2)
void conv2_mma(const float* __restrict__ bias)
{
    extern __shared__ __align__(128) char smraw[];
    const unsigned sb = smem_u32(smraw);
    const int tid  = threadIdx.x;
    const int lane = tid & 31;
    const int wid  = tid >> 5;
    const int wm   = wid & 3;      // m-warp 0..3 (32 rows each)
    const int wn   = wid >> 2;     // n-warp 0..1 (64 ch each)
    const int m0   = blockIdx.x * 128;
    const int ch0  = blockIdx.y * 128;

    // ---- fill-state: this thread fills k-pair p for rows rbase+16*i ----
    const int p     = tid & 15;
    const int rbase = tid >> 4;
    int ic, ky, kx;
    { int k0 = 2*p; ic = 0; ky = k0/9; kx = k0 - 9*ky; }
    int naddr[8];
#pragma unroll
    for (int i = 0; i < 8; ++i) {
        int nsp = m0 + rbase + 16*i;
        int b = nsp / P2, rem = nsp - b*P2;
        int oy = rem / OH2, ox = rem - oy*OH2;
        naddr[i] = b*(MCH*NPIX1) + oy*(2*OH1) + ox*2;
    }

    float acc[2][8][4];
#pragma unroll
    for (int mt = 0; mt < 2; ++mt)
#pragma unroll
        for (int nt = 0; nt < 8; ++nt)
#pragma unroll
            for (int q = 0; q < 4; ++q) acc[mt][nt][q] = 0.f;

    // ldmatrix lane address components
    const int arow = (lane & 7) + ((lane >> 3) & 1)*8;
    const int acol = ((lane >> 4) & 1)*8;
    const int brow = (lane & 7) + ((lane >> 4) & 1)*8;
    const int bcol = ((lane >> 3) & 1)*8;
    const unsigned aoff = (unsigned)((wm*32 + arow)*80 + acol*2);
    const unsigned boff = (unsigned)(OFF_BHI + (wn*64 + brow)*80 + bcol*2);

    unsigned wreg[16];

    // load A(next chunk) pixels into registers; advances k-state
    auto LDG_A = [&]() {
        int ka  = ic*NPIX1 + ky*OH1 + kx;
        int ka2 = ka + ((kx == 8) ? ((ky == 8) ? (NPIX1 - 8*OH1 - 8) : (OH1 - 8)) : 1);
#pragma unroll
        for (int i = 0; i < 8; ++i) {
            wreg[2*i]   = g_h1p[naddr[i] + ka];
            wreg[2*i+1] = g_h1p[naddr[i] + ka2];
        }
        kx += 5; ky += 3;                 // advance k by 32 (= 3*9 + 5)
        if (kx >= 9) { kx -= 9; ++ky; }
        if (ky >= 9) { ky -= 9; ++ic; }
    };
    // split + store the prefetched A registers into stage st
    auto STS_A = [&](unsigned st) {
#pragma unroll
        for (int i = 0; i < 8; ++i) {
            unsigned hi01 = __byte_perm(wreg[2*i], wreg[2*i+1], 0x5410);
            unsigned lo01 = __byte_perm(wreg[2*i], wreg[2*i+1], 0x7632);
            unsigned d = st + (unsigned)(rbase + 16*i)*80 + 4u*p;
            asm volatile("st.shared.b32 [%0], %1;" :: "r"(d), "r"(hi01) : "memory");
            asm volatile("st.shared.b32 [%0], %1;" :: "r"(d + OFF_ALO), "r"(lo01) : "memory");
        }
    };
    // B weights via cp.async from linear pre-split image
    auto B_FILL = [&](int c, unsigned st) {
#pragma unroll
        for (int it = 0; it < 4; ++it) {
            int g     = tid + 256*it;
            int plane = g >> 9;
            int chrow = (g >> 2) & 127;
            int j     = g & 3;
            const unsigned* src = g_w2img + (((c*2 + plane)*256) + ch0 + chrow)*16 + j*4;
            unsigned dst = st + (plane ? OFF_BLO : OFF_BHI) + (unsigned)chrow*80 + j*16;
            cp16(dst, src);
        }
        cp_commit();
    };

    // prologue: fill stage 0
    LDG_A();
    B_FILL(0, sb);
    STS_A(sb);
    cp_wait<0>();
    __syncthreads();

#pragma unroll 1
    for (int c = 0; c < NCH; ++c) {
        const unsigned st  = sb + (unsigned)(c & 1)*STAGE_B;
        const unsigned st2 = sb + (unsigned)((c + 1) & 1)*STAGE_B;
        const bool pre = (c + 1 < NCH);

        if (pre) {
            LDG_A();            // latency covered by the MMA section below
            B_FILL(c + 1, st2);
        }

#pragma unroll
        for (int kh = 0; kh < 2; ++kh) {
            const unsigned ka_ = st + aoff + kh*32;
            const unsigned kb_ = st + boff + kh*32;
            unsigned ah[2][4], al[2][4], bb[4][4];
            ldm4(ah[0], ka_);
            ldm4(ah[1], ka_ + 1280);
            ldm4(al[0], ka_ + OFF_ALO);
            ldm4(al[1], ka_ + OFF_ALO + 1280);
#pragma unroll
            for (int j = 0; j < 4; ++j) ldm4(bb[j], kb_ + j*1280);
#pragma unroll
            for (int mt = 0; mt < 2; ++mt)
#pragma unroll
                for (int j = 0; j < 4; ++j) {
                    mma16816(acc[mt][2*j],   ah[mt], bb[j][0], bb[j][1]);
                    mma16816(acc[mt][2*j+1], ah[mt], bb[j][2], bb[j][3]);
                    mma16816(acc[mt][2*j],   al[mt], bb[j][0], bb[j][1]);
                    mma16816(acc[mt][2*j+1], al[mt], bb[j][2], bb[j][3]);
                }
#pragma unroll
            for (int j = 0; j < 4; ++j) ldm4(bb[j], kb_ + (OFF_BLO - OFF_BHI) + j*1280);
#pragma unroll
            for (int mt = 0; mt < 2; ++mt)
#pragma unroll
                for (int j = 0; j < 4; ++j) {
                    mma16816(acc[mt][2*j],   ah[mt], bb[j][0], bb[j][1]);
                    mma16816(acc[mt][2*j+1], ah[mt], bb[j][2], bb[j][3]);
                }
        }

        if (pre) STS_A(st2);   // writes the other buffer; safe pre-sync
        cp_wait<0>();          // B(c+1) landed
        __syncthreads();       // stage c free, stage c+1 visible
    }

    // ---- epilogue: acc + bias -> caps layout ----
#pragma unroll
    for (int mt = 0; mt < 2; ++mt) {
        int rowA = m0 + wm*32 + mt*16 + (lane >> 2);
#pragma unroll
        for (int half = 0; half < 2; ++half) {
            int nsp = rowA + half*8;
            int b = nsp / P2, pp = nsp - b*P2;
            long obase = ((long)(b*RR))*P2 + pp;
#pragma unroll
            for (int nt = 0; nt < 8; ++nt) {
                int chb = ch0 + wn*64 + nt*8 + (lane & 3)*2;
#pragma unroll
                for (int e = 0; e < 2; ++e) {
                    int ch = chb + e;
                    float v = acc[mt][nt][half*2 + e] + bias[ch];
                    int rr = ch >> 3, dd = ch & 7;
                    g_caps[(obase + (long)rr*P2)*DD + dd] = v;
                }
            }
        }
    }
}

// ---------------- squash primary capsules (in place) ----------------
__global__ void squash_caps_kernel() {
    int v = blockIdx.x * 256 + threadIdx.x;
    if (v >= NB*RR*P2) return;
    float4 lo = *(float4*)&g_caps[v*8];
    float4 hi = *(float4*)&g_caps[v*8 + 4];
    float norm = lo.x*lo.x + lo.y*lo.y + lo.z*lo.z + lo.w*lo.w
               + hi.x*hi.x + hi.y*hi.y + hi.z*hi.z + hi.w*hi.w;
    float scale = norm / ((1.f + norm) * sqrtf(norm + 1e-8f));
    lo.x *= scale; lo.y *= scale; lo.z *= scale; lo.w *= scale;
    hi.x *= scale; hi.y *= scale; hi.z *= scale; hi.w *= scale;
    *(float4*)&g_caps[v*8]     = lo;
    *(float4*)&g_caps[v*8 + 4] = hi;
}

// ---------------- WV[b,r,c,i] = sum_o route_w[r,c,i,o] * v[b,c,o] ----------------
__global__ void wv_kernel(const float* __restrict__ route_w) {
    int idx = blockIdx.x * 128 + threadIdx.x;
    if (idx >= NB*RR*CC*DD) return;
    int b    = idx / (RR*CC*DD);
    int rem  = idx - b*(RR*CC*DD);
    int r    = rem / (CC*DD);
    int rem2 = rem - r*(CC*DD);
    int c    = rem2 / DD;
    int i    = rem2 - c*DD;
    const float* w = route_w + ((r*CC + c)*DD + i)*OO;
    const float* v = g_v + (b*CC + c)*OO;
    float acc = 0.f;
#pragma unroll
    for (int o = 0; o < OO; ++o) acc += w[o] * v[o];
    g_WV[idx] = acc;
}

// ---------------- routing pass ----------------
template<int MODE>
__global__ void pass_kernel() {
    const int b = blockIdx.x, r = blockIdx.y;
    const int tid = threadIdx.x;   // 64 threads
    __shared__ float sWV[CC*DD];
    __shared__ float sG[2][CC*DD];

    if (MODE >= 2) {
        for (int j = tid; j < CC*DD; j += 64)
            sWV[j] = g_WV[(b*RR + r)*CC*DD + j];
    }
    __syncthreads();

    float Gp[CC*DD];
#pragma unroll
    for (int j = 0; j < CC*DD; ++j) Gp[j] = 0.f;

    const float* capbase = g_caps + (size_t)(b*RR + r)*P2*DD;

#pragma unroll 1
    for (int pi = 0; pi < 9; ++pi) {
        int p = pi*64 + tid;
        float4 l0 = *(const float4*)(capbase + p*8);
        float4 l1 = *(const float4*)(capbase + p*8 + 4);
        float cv[8] = { l0.x, l0.y, l0.z, l0.w, l1.x, l1.y, l1.z, l1.w };

        float cw[CC];
        if (MODE == 1) {
#pragma unroll
            for (int c = 0; c < CC; ++c) cw[c] = 0.1f;
        } else {
            float bvv[CC];
            long bidx = ((long)b*RR*P2 + (long)r*P2 + p)*CC;
#pragma unroll
            for (int c = 0; c < CC; ++c) {
                float t = 0.f;
#pragma unroll
                for (int i = 0; i < 8; ++i) t += cv[i] * sWV[c*8 + i];
                bvv[c] = ((MODE == 3) ? g_blog[bidx + c] : 0.f) + t;
                if (MODE == 2) g_blog[bidx + c] = bvv[c];
            }
            float mx = bvv[0];
#pragma unroll
            for (int c = 1; c < CC; ++c) mx = fmaxf(mx, bvv[c]);
            float sum = 0.f;
#pragma unroll
            for (int c = 0; c < CC; ++c) { cw[c] = __expf(bvv[c] - mx); sum += cw[c]; }
            float inv = 1.f / sum;
#pragma unroll
            for (int c = 0; c < CC; ++c) cw[c] *= inv;
        }
#pragma unroll
        for (int c = 0; c < CC; ++c)
#pragma unroll
            for (int i = 0; i < 8; ++i) Gp[c*8 + i] += cw[c] * cv[i];
    }

    int wid2 = tid >> 5, lane = tid & 31;
#pragma unroll
    for (int j = 0; j < CC*DD; ++j) {
        float val = Gp[j];
#pragma unroll
        for (int s = 16; s > 0; s >>= 1) val += __shfl_xor_sync(0xffffffffu, val, s);
        if (lane == 0) sG[wid2][j] = val;
    }
    __syncthreads();
    for (int j = tid; j < CC*DD; j += 64)
        g_G[(b*RR + r)*CC*DD + j] = sG[0][j] + sG[1][j];
}

// ---------------- s = G . W ; v = squash(s) ----------------
__global__ void sv_kernel(const float* __restrict__ route_w, float* __restrict__ dout) {
    const int b = blockIdx.x;
    const int tid = threadIdx.x;     // 160 threads = (c,o)
    __shared__ float sGb[RR*CC*DD];
    __shared__ float ss[CC*OO];

    for (int j = tid; j < RR*CC*DD; j += CC*OO) sGb[j] = g_G[b*RR*CC*DD + j];
    __syncthreads();

    const int c = tid / OO, o = tid - (tid / OO)*OO;
    float s = 0.f;
#pragma unroll 1
    for (int r = 0; r < RR; ++r) {
#pragma unroll
        for (int i = 0; i < DD; ++i)
            s += sGb[(r*CC + c)*DD + i] * route_w[((r*CC + c)*DD + i)*OO + o];
    }
    ss[tid] = s;
    __syncthreads();
    float norm = 0.f;
#pragma unroll
    for (int oo = 0; oo < OO; ++oo) { float t = ss[c*OO + oo]; norm += t*t; }
    float scale = norm / ((1.f + norm) * sqrtf(norm + 1e-8f));
    float val = scale * s;
    g_v[b*CC*OO + tid] = val;
    if (dout) dout[b*CC*OO + tid] = val;
}

// ---------------- launcher ----------------
extern "C" void kernel_launch(void* const* d_in, const int* in_sizes, int n_in,
                              void* d_out, int out_size)
{
    const float* x  = (const float*)d_in[0];   // [32,3,64,64]
    const float* w1 = (const float*)d_in[1];   // [256,3,9,9]
    const float* b1 = (const float*)d_in[2];   // [256]
    const float* w2 = (const float*)d_in[3];   // [256,256,9,9]
    const float* b2 = (const float*)d_in[4];   // [256]
    const float* rw = (const float*)d_in[5];   // [32,10,8,16]
    float* out = (float*)d_out;

    static int smem_set = 0;
    if (!smem_set) {
        cudaFuncSetAttribute(conv2_mma,
                             cudaFuncAttributeMaxDynamicSharedMemorySize, CONV2_SMEM);
        smem_set = 1;
    }

    // weight prep
    wt1_kernel<<<(K1PAD*MCH + 255)/256, 256>>>(w1);
    wsplit_kernel<<<K2/2, 256>>>(w2);

    // conv1 -> g_h1p (packed bf16-split)
    conv1_kernel<<<dim3(N1/128, 2), 256>>>(x, b1);
    // conv2 -> g_caps (mma.sync tensor cores)
    conv2_mma<<<dim3(N2/128, 2), 256, CONV2_SMEM>>>(b2);
    // squash primary caps
    squash_caps_kernel<<<(NB*RR*P2 + 255)/256, 256>>>();

    // routing iteration 1
    pass_kernel<1><<<dim3(NB, RR), 64>>>();
    sv_kernel<<<NB, CC*OO>>>(rw, nullptr);
    // routing iteration 2
    wv_kernel<<<(NB*RR*CC*DD + 127)/128, 128>>>(rw);
    pass_kernel<2><<<dim3(NB, RR), 64>>>();
    sv_kernel<<<NB, CC*OO>>>(rw, nullptr);
    // routing iteration 3 (final)
    wv_kernel<<<(NB*RR*CC*DD + 127)/128, 128>>>(rw);
    pass_kernel<3><<<dim3(NB, RR), 64>>>();
    sv_kernel<<<NB, CC*OO>>>(rw, out);
    (void)out_size;
}